// round 1
// baseline (speedup 1.0000x reference)
#include <cuda_runtime.h>
#include <math.h>

#define BM 128
#define BN 128
#define BK 16
#define SMP (BM + 4)

#define BATCH 4
#define C 512
#define CQ 64
#define N 4096

// Scratch (device globals — no allocations allowed)
__device__ float g_q[(size_t)BATCH * CQ * N];
__device__ float g_k[(size_t)BATCH * CQ * N];
__device__ float g_v[(size_t)BATCH * C * N];
__device__ float g_E[(size_t)BATCH * N * N];   // 268 MB attention scratch

// ---------------------------------------------------------------------------
// Projection: Y[b, m, n] = sum_c W[m,c] * x[b,c,n] + bias[m]
// which: 0 -> g_q (M=64), 1 -> g_k (M=64), 2 -> g_v (M=512)
// ---------------------------------------------------------------------------
__global__ __launch_bounds__(256) void proj_kernel(
    const float* __restrict__ W, const float* __restrict__ bias,
    const float* __restrict__ x, int which, int M)
{
    float* Yg = (which == 0) ? g_q : (which == 1) ? g_k : g_v;
    int b = blockIdx.z;
    const float* X = x + (size_t)b * C * N;
    float* Y = Yg + (size_t)b * M * N;
    int row0 = blockIdx.y * BM;
    int col0 = blockIdx.x * BN;

    __shared__ __align__(16) float As[BK][SMP];
    __shared__ __align__(16) float Bs[BK][SMP];

    int tid = threadIdx.x;
    int tx = tid & 15;
    int ty = tid >> 4;

    float acc[8][8];
#pragma unroll
    for (int i = 0; i < 8; i++)
#pragma unroll
        for (int j = 0; j < 8; j++) acc[i][j] = 0.f;

    for (int k0 = 0; k0 < C; k0 += BK) {
        // A = W (row-major M x C), store transposed: As[k][m]
#pragma unroll
        for (int l = 0; l < 8; l++) {
            int idx = tid + l * 256;
            int i = idx >> 4, j = idx & 15;
            int r = row0 + i;
            As[j][i] = (r < M) ? W[(size_t)r * C + k0 + j] : 0.f;
        }
        // B = X (C x N), natural: Bs[k][n]
#pragma unroll
        for (int l = 0; l < 8; l++) {
            int idx = tid + l * 256;
            int j = idx >> 7, n = idx & 127;
            Bs[j][n] = X[(size_t)(k0 + j) * N + col0 + n];
        }
        __syncthreads();
#pragma unroll
        for (int kk = 0; kk < BK; kk++) {
            float4 a0 = *(const float4*)&As[kk][ty * 4];
            float4 a1 = *(const float4*)&As[kk][ty * 4 + 64];
            float4 b0 = *(const float4*)&Bs[kk][tx * 4];
            float4 b1 = *(const float4*)&Bs[kk][tx * 4 + 64];
            float a[8] = {a0.x, a0.y, a0.z, a0.w, a1.x, a1.y, a1.z, a1.w};
            float bb[8] = {b0.x, b0.y, b0.z, b0.w, b1.x, b1.y, b1.z, b1.w};
#pragma unroll
            for (int i = 0; i < 8; i++)
#pragma unroll
                for (int j = 0; j < 8; j++)
                    acc[i][j] += a[i] * bb[j];
        }
        __syncthreads();
    }

#pragma unroll
    for (int ih = 0; ih < 2; ih++) {
#pragma unroll
        for (int i2 = 0; i2 < 4; i2++) {
            int r = row0 + ih * 64 + ty * 4 + i2;
            if (r >= M) continue;
            float bv_ = bias[r];
            int ar = ih * 4 + i2;
#pragma unroll
            for (int jh = 0; jh < 2; jh++) {
                float4 o;
                o.x = acc[ar][jh * 4 + 0] + bv_;
                o.y = acc[ar][jh * 4 + 1] + bv_;
                o.z = acc[ar][jh * 4 + 2] + bv_;
                o.w = acc[ar][jh * 4 + 3] + bv_;
                *(float4*)&Y[(size_t)r * N + col0 + jh * 64 + tx * 4] = o;
            }
        }
    }
}

// ---------------------------------------------------------------------------
// Energy: E[b, n, m] = sum_o q[b,o,n] * k[b,o,m]     (TN gemm, K=64)
// ---------------------------------------------------------------------------
__global__ __launch_bounds__(256) void energy_kernel()
{
    int b = blockIdx.z;
    const float* Q  = g_q + (size_t)b * CQ * N;
    const float* Km = g_k + (size_t)b * CQ * N;
    float* E = g_E + (size_t)b * N * N;
    int row0 = blockIdx.y * BM;   // query index n
    int col0 = blockIdx.x * BN;   // key index m

    __shared__ __align__(16) float As[BK][SMP];
    __shared__ __align__(16) float Bs[BK][SMP];

    int tid = threadIdx.x;
    int tx = tid & 15;
    int ty = tid >> 4;

    float acc[8][8];
#pragma unroll
    for (int i = 0; i < 8; i++)
#pragma unroll
        for (int j = 0; j < 8; j++) acc[i][j] = 0.f;

    for (int k0 = 0; k0 < CQ; k0 += BK) {
#pragma unroll
        for (int l = 0; l < 8; l++) {
            int idx = tid + l * 256;
            int j = idx >> 7, i = idx & 127;
            As[j][i] = Q[(size_t)(k0 + j) * N + row0 + i];
        }
#pragma unroll
        for (int l = 0; l < 8; l++) {
            int idx = tid + l * 256;
            int j = idx >> 7, i = idx & 127;
            Bs[j][i] = Km[(size_t)(k0 + j) * N + col0 + i];
        }
        __syncthreads();
#pragma unroll
        for (int kk = 0; kk < BK; kk++) {
            float4 a0 = *(const float4*)&As[kk][ty * 4];
            float4 a1 = *(const float4*)&As[kk][ty * 4 + 64];
            float4 b0 = *(const float4*)&Bs[kk][tx * 4];
            float4 b1 = *(const float4*)&Bs[kk][tx * 4 + 64];
            float a[8] = {a0.x, a0.y, a0.z, a0.w, a1.x, a1.y, a1.z, a1.w};
            float bb[8] = {b0.x, b0.y, b0.z, b0.w, b1.x, b1.y, b1.z, b1.w};
#pragma unroll
            for (int i = 0; i < 8; i++)
#pragma unroll
                for (int j = 0; j < 8; j++)
                    acc[i][j] += a[i] * bb[j];
        }
        __syncthreads();
    }

#pragma unroll
    for (int ih = 0; ih < 2; ih++) {
#pragma unroll
        for (int i2 = 0; i2 < 4; i2++) {
            int r = row0 + ih * 64 + ty * 4 + i2;
            int ar = ih * 4 + i2;
#pragma unroll
            for (int jh = 0; jh < 2; jh++) {
                float4 o;
                o.x = acc[ar][jh * 4 + 0];
                o.y = acc[ar][jh * 4 + 1];
                o.z = acc[ar][jh * 4 + 2];
                o.w = acc[ar][jh * 4 + 3];
                *(float4*)&E[(size_t)r * N + col0 + jh * 64 + tx * 4] = o;
            }
        }
    }
}

// ---------------------------------------------------------------------------
// Row softmax in place over E rows of length 4096. One CTA per row.
// ---------------------------------------------------------------------------
__global__ __launch_bounds__(256) void softmax_kernel()
{
    size_t row = blockIdx.x;                // 0 .. BATCH*N-1
    float* E = g_E + row * (size_t)N;
    int tid = threadIdx.x;
    int wid = tid >> 5, lane = tid & 31;

    float4 v[4];
#pragma unroll
    for (int l = 0; l < 4; l++) v[l] = ((const float4*)E)[tid + l * 256];

    float mx = -1e30f;
#pragma unroll
    for (int l = 0; l < 4; l++)
        mx = fmaxf(mx, fmaxf(fmaxf(v[l].x, v[l].y), fmaxf(v[l].z, v[l].w)));
#pragma unroll
    for (int o = 16; o > 0; o >>= 1)
        mx = fmaxf(mx, __shfl_xor_sync(0xffffffffu, mx, o));

    __shared__ float red[8];
    if (lane == 0) red[wid] = mx;
    __syncthreads();
    float bm = red[0];
#pragma unroll
    for (int i = 1; i < 8; i++) bm = fmaxf(bm, red[i]);
    __syncthreads();

    float s = 0.f;
#pragma unroll
    for (int l = 0; l < 4; l++) {
        v[l].x = __expf(v[l].x - bm); s += v[l].x;
        v[l].y = __expf(v[l].y - bm); s += v[l].y;
        v[l].z = __expf(v[l].z - bm); s += v[l].z;
        v[l].w = __expf(v[l].w - bm); s += v[l].w;
    }
#pragma unroll
    for (int o = 16; o > 0; o >>= 1)
        s += __shfl_xor_sync(0xffffffffu, s, o);
    if (lane == 0) red[wid] = s;
    __syncthreads();
    float tot = 0.f;
#pragma unroll
    for (int i = 0; i < 8; i++) tot += red[i];
    float inv = 1.f / tot;

#pragma unroll
    for (int l = 0; l < 4; l++) {
        v[l].x *= inv; v[l].y *= inv; v[l].z *= inv; v[l].w *= inv;
        ((float4*)E)[tid + l * 256] = v[l];
    }
}

// ---------------------------------------------------------------------------
// Out: out[b,c,n] = gamma * (sum_m v[b,c,m] * P[b,n,m]) + x[b,c,n]  (NT gemm)
// ---------------------------------------------------------------------------
__global__ __launch_bounds__(256) void out_kernel(
    const float* __restrict__ x, const float* __restrict__ gamma,
    float* __restrict__ out)
{
    int b = blockIdx.z;
    const float* V = g_v + (size_t)b * C * N;
    const float* P = g_E + (size_t)b * N * N;
    int row0 = blockIdx.y * BM;   // channel c
    int col0 = blockIdx.x * BN;   // position n

    __shared__ __align__(16) float As[BK][SMP];
    __shared__ __align__(16) float Bs[BK][SMP];

    int tid = threadIdx.x;
    int tx = tid & 15;
    int ty = tid >> 4;

    float acc[8][8];
#pragma unroll
    for (int i = 0; i < 8; i++)
#pragma unroll
        for (int j = 0; j < 8; j++) acc[i][j] = 0.f;

    for (int m0 = 0; m0 < N; m0 += BK) {
        // A = V (C x N), K-contiguous: transpose into As[k][c]
#pragma unroll
        for (int l = 0; l < 8; l++) {
            int idx = tid + l * 256;
            int i = idx >> 4, j = idx & 15;
            As[j][i] = V[(size_t)(row0 + i) * N + m0 + j];
        }
        // B = P (N x N), K-contiguous: transpose into Bs[k][n]
#pragma unroll
        for (int l = 0; l < 8; l++) {
            int idx = tid + l * 256;
            int i = idx >> 4, j = idx & 15;
            Bs[j][i] = P[(size_t)(col0 + i) * N + m0 + j];
        }
        __syncthreads();
#pragma unroll
        for (int kk = 0; kk < BK; kk++) {
            float4 a0 = *(const float4*)&As[kk][ty * 4];
            float4 a1 = *(const float4*)&As[kk][ty * 4 + 64];
            float4 b0 = *(const float4*)&Bs[kk][tx * 4];
            float4 b1 = *(const float4*)&Bs[kk][tx * 4 + 64];
            float a[8] = {a0.x, a0.y, a0.z, a0.w, a1.x, a1.y, a1.z, a1.w};
            float bb[8] = {b0.x, b0.y, b0.z, b0.w, b1.x, b1.y, b1.z, b1.w};
#pragma unroll
            for (int i = 0; i < 8; i++)
#pragma unroll
                for (int j = 0; j < 8; j++)
                    acc[i][j] += a[i] * bb[j];
        }
        __syncthreads();
    }

    float g = gamma[0];
#pragma unroll
    for (int ih = 0; ih < 2; ih++) {
#pragma unroll
        for (int i2 = 0; i2 < 4; i2++) {
            int r = row0 + ih * 64 + ty * 4 + i2;   // channel
            int ar = ih * 4 + i2;
#pragma unroll
            for (int jh = 0; jh < 2; jh++) {
                int cn = col0 + jh * 64 + tx * 4;
                size_t base = (size_t)b * C * N + (size_t)r * N + cn;
                float4 xv = *(const float4*)&x[base];
                float4 o;
                o.x = g * acc[ar][jh * 4 + 0] + xv.x;
                o.y = g * acc[ar][jh * 4 + 1] + xv.y;
                o.z = g * acc[ar][jh * 4 + 2] + xv.z;
                o.w = g * acc[ar][jh * 4 + 3] + xv.w;
                *(float4*)&out[base] = o;
            }
        }
    }
}

// ---------------------------------------------------------------------------
extern "C" void kernel_launch(void* const* d_in, const int* in_sizes, int n_in,
                              void* d_out, int out_size)
{
    const float* x     = (const float*)d_in[0];
    const float* Wq    = (const float*)d_in[1];
    const float* bq    = (const float*)d_in[2];
    const float* Wk    = (const float*)d_in[3];
    const float* bk    = (const float*)d_in[4];
    const float* Wv    = (const float*)d_in[5];
    const float* bv    = (const float*)d_in[6];
    const float* gamma = (const float*)d_in[7];
    float* out = (float*)d_out;

    dim3 blk(256);

    // Projections
    proj_kernel<<<dim3(N / BN, 1, BATCH), blk>>>(Wq, bq, x, 0, CQ);
    proj_kernel<<<dim3(N / BN, 1, BATCH), blk>>>(Wk, bk, x, 1, CQ);
    proj_kernel<<<dim3(N / BN, C / BM, BATCH), blk>>>(Wv, bv, x, 2, C);

    // Energy (q^T k), then softmax over keys
    energy_kernel<<<dim3(N / BN, N / BM, BATCH), blk>>>();
    softmax_kernel<<<BATCH * N, 256>>>();

    // out = gamma * (V @ A^T) + x
    out_kernel<<<dim3(N / BN, C / BM, BATCH), blk>>>(x, gamma, out);
}

// round 2
// speedup vs baseline: 1.3638x; 1.3638x over previous
#include <cuda_runtime.h>
#include <math.h>

#define BM 128
#define BN 128
#define BK 16
#define ASTR 132          // padded stride for transposed A tiles
#define BATCH 4
#define C 512
#define CQ 64
#define N 4096
#define MSPLIT 8

// ---------------- scratch (device globals; no allocations allowed) ----------
__device__ float g_q[(size_t)BATCH * CQ * N];
__device__ float g_k[(size_t)BATCH * CQ * N];
__device__ float g_v[(size_t)BATCH * C * N];
__device__ float g_E[(size_t)BATCH * N * N];     // Et[m][n], then exp(Et-max)
__device__ int   g_colmax[BATCH * N];
__device__ float g_sumpart[MSPLIT][BATCH * N];
__device__ float g_colinv[BATCH * N];

// ---------------- helpers ---------------------------------------------------
__device__ __forceinline__ unsigned smem_u32(const void* p) {
    return (unsigned)__cvta_generic_to_shared(p);
}
__device__ __forceinline__ void cpa16(unsigned s, const float* g) {
    asm volatile("cp.async.cg.shared.global [%0], [%1], 16;\n" :: "r"(s), "l"(g));
}
__device__ __forceinline__ void cpcommit() { asm volatile("cp.async.commit_group;\n" ::); }
__device__ __forceinline__ void cpwait0()  { asm volatile("cp.async.wait_group 0;\n" ::); }

__device__ __forceinline__ int f2o(float f) {          // order-preserving float->int
    int i = __float_as_int(f);
    return i >= 0 ? i : i ^ 0x7FFFFFFF;
}
__device__ __forceinline__ float o2f(int i) {
    return __int_as_float(i >= 0 ? i : i ^ 0x7FFFFFFF);
}

template <int ASTRIDE>
__device__ __forceinline__ void mm_tile(const float* __restrict__ As,
                                        const float* __restrict__ Bs,
                                        float acc[8][8], int tx, int ty) {
#pragma unroll
    for (int kk = 0; kk < BK; kk++) {
        float4 a0 = *(const float4*)(As + kk * ASTRIDE + ty * 4);
        float4 a1 = *(const float4*)(As + kk * ASTRIDE + ty * 4 + 64);
        float4 b0 = *(const float4*)(Bs + kk * BN + tx * 4);
        float4 b1 = *(const float4*)(Bs + kk * BN + tx * 4 + 64);
        float a[8] = {a0.x, a0.y, a0.z, a0.w, a1.x, a1.y, a1.z, a1.w};
        float b[8] = {b0.x, b0.y, b0.z, b0.w, b1.x, b1.y, b1.z, b1.w};
#pragma unroll
        for (int i = 0; i < 8; i++)
#pragma unroll
            for (int j = 0; j < 8; j++)
                acc[i][j] += a[i] * b[j];
    }
}

// ---------------------------------------------------------------------------
// init: colmax = -inf (ordered-int INT_MIN)
// ---------------------------------------------------------------------------
__global__ void init_kernel() {
    int i = blockIdx.x * 256 + threadIdx.x;
    g_colmax[i] = 0x80000000;
}

// ---------------------------------------------------------------------------
// Projection: Y[b, m, n] = sum_c W[m,c]*x[b,c,n] + bias[m]
// A = W (transpose via LDG+STS), B = x (natural, cp.async), double-buffered.
// ---------------------------------------------------------------------------
__global__ __launch_bounds__(256) void proj_kernel(
    const float* __restrict__ W, const float* __restrict__ bias,
    const float* __restrict__ x, int which, int M)
{
    float* Yg = (which == 0) ? g_q : (which == 1) ? g_k : g_v;
    int b = blockIdx.z;
    const float* X = x + (size_t)b * C * N;
    float* Y = Yg + (size_t)b * M * N;
    int row0 = blockIdx.y * BM;
    int col0 = blockIdx.x * BN;

    __shared__ __align__(16) float As[2][BK * ASTR];
    __shared__ __align__(16) float Bs[2][BK * BN];

    int tid = threadIdx.x;
    int tx = tid & 15, ty = tid >> 4;

    int ar = tid >> 2;            // 0..63 (A row within tile)
    int ak = (tid & 3) * 4;       // A k-offset (float4)
    int bkr = tid >> 4;           // 0..15 (B k-row)
    int bn  = (tid & 15) * 4;     // B n-offset (float4)

    float acc[8][8];
#pragma unroll
    for (int i = 0; i < 8; i++)
#pragma unroll
        for (int j = 0; j < 8; j++) acc[i][j] = 0.f;

    const int KT = C / BK;
    float4 av0, av1;
    float4 zero4 = make_float4(0.f, 0.f, 0.f, 0.f);

    // prologue
    {
        int r0 = row0 + ar, r1 = row0 + ar + 64;
        av0 = (r0 < M) ? *(const float4*)&W[(size_t)r0 * C + ak] : zero4;
        av1 = (r1 < M) ? *(const float4*)&W[(size_t)r1 * C + ak] : zero4;
        unsigned s = smem_u32(&Bs[0][bkr * BN + bn]);
        cpa16(s, &X[(size_t)bkr * N + col0 + bn]);
        cpa16(s + 64 * 4, &X[(size_t)bkr * N + col0 + bn + 64]);
        cpcommit();
        float* A = As[0];
        A[(ak + 0) * ASTR + ar] = av0.x; A[(ak + 1) * ASTR + ar] = av0.y;
        A[(ak + 2) * ASTR + ar] = av0.z; A[(ak + 3) * ASTR + ar] = av0.w;
        A[(ak + 0) * ASTR + ar + 64] = av1.x; A[(ak + 1) * ASTR + ar + 64] = av1.y;
        A[(ak + 2) * ASTR + ar + 64] = av1.z; A[(ak + 3) * ASTR + ar + 64] = av1.w;
    }

    for (int kt = 0; kt < KT; kt++) {
        cpwait0();
        __syncthreads();
        int nk = kt + 1;
        if (nk < KT) {
            int k0 = nk * BK;
            unsigned s = smem_u32(&Bs[nk & 1][bkr * BN + bn]);
            cpa16(s, &X[(size_t)(k0 + bkr) * N + col0 + bn]);
            cpa16(s + 64 * 4, &X[(size_t)(k0 + bkr) * N + col0 + bn + 64]);
            cpcommit();
            int r0 = row0 + ar, r1 = row0 + ar + 64;
            av0 = (r0 < M) ? *(const float4*)&W[(size_t)r0 * C + k0 + ak] : zero4;
            av1 = (r1 < M) ? *(const float4*)&W[(size_t)r1 * C + k0 + ak] : zero4;
        }
        mm_tile<ASTR>(As[kt & 1], Bs[kt & 1], acc, tx, ty);
        if (nk < KT) {
            float* A = As[nk & 1];
            A[(ak + 0) * ASTR + ar] = av0.x; A[(ak + 1) * ASTR + ar] = av0.y;
            A[(ak + 2) * ASTR + ar] = av0.z; A[(ak + 3) * ASTR + ar] = av0.w;
            A[(ak + 0) * ASTR + ar + 64] = av1.x; A[(ak + 1) * ASTR + ar + 64] = av1.y;
            A[(ak + 2) * ASTR + ar + 64] = av1.z; A[(ak + 3) * ASTR + ar + 64] = av1.w;
        }
    }

#pragma unroll
    for (int ih = 0; ih < 2; ih++) {
#pragma unroll
        for (int i2 = 0; i2 < 4; i2++) {
            int r = row0 + ih * 64 + ty * 4 + i2;
            if (r >= M) continue;
            float bv_ = bias[r];
            int arr = ih * 4 + i2;
#pragma unroll
            for (int jh = 0; jh < 2; jh++) {
                float4 o;
                o.x = acc[arr][jh * 4 + 0] + bv_;
                o.y = acc[arr][jh * 4 + 1] + bv_;
                o.z = acc[arr][jh * 4 + 2] + bv_;
                o.w = acc[arr][jh * 4 + 3] + bv_;
                *(float4*)&Y[(size_t)r * N + col0 + jh * 64 + tx * 4] = o;
            }
        }
    }
}

// ---------------------------------------------------------------------------
// Energy (transposed): Et[b, m, n] = sum_o k[b,o,m] * q[b,o,n]
// Both operands natural layout -> cp.async both sides. Fused column-max atomics.
// ---------------------------------------------------------------------------
__global__ __launch_bounds__(256) void energy_kernel()
{
    int b = blockIdx.z;
    const float* Km = g_k + (size_t)b * CQ * N;
    const float* Q  = g_q + (size_t)b * CQ * N;
    float* E = g_E + (size_t)b * N * N;
    int row0 = blockIdx.y * BM;   // m (key index)
    int col0 = blockIdx.x * BN;   // n (query index)

    __shared__ __align__(16) float As[2][BK * BN];
    __shared__ __align__(16) float Bs[2][BK * BN];

    int tid = threadIdx.x;
    int tx = tid & 15, ty = tid >> 4;
    int kr = tid >> 4;            // 0..15
    int nq = (tid & 15) * 4;

    float acc[8][8];
#pragma unroll
    for (int i = 0; i < 8; i++)
#pragma unroll
        for (int j = 0; j < 8; j++) acc[i][j] = 0.f;

    const int KT = CQ / BK;  // 4

    // prologue
    {
        unsigned sa = smem_u32(&As[0][kr * BN + nq]);
        cpa16(sa, &Km[(size_t)kr * N + row0 + nq]);
        cpa16(sa + 64 * 4, &Km[(size_t)kr * N + row0 + nq + 64]);
        unsigned sb = smem_u32(&Bs[0][kr * BN + nq]);
        cpa16(sb, &Q[(size_t)kr * N + col0 + nq]);
        cpa16(sb + 64 * 4, &Q[(size_t)kr * N + col0 + nq + 64]);
        cpcommit();
    }

    for (int kt = 0; kt < KT; kt++) {
        cpwait0();
        __syncthreads();
        int nk = kt + 1;
        if (nk < KT) {
            int k0 = nk * BK;
            unsigned sa = smem_u32(&As[nk & 1][kr * BN + nq]);
            cpa16(sa, &Km[(size_t)(k0 + kr) * N + row0 + nq]);
            cpa16(sa + 64 * 4, &Km[(size_t)(k0 + kr) * N + row0 + nq + 64]);
            unsigned sb = smem_u32(&Bs[nk & 1][kr * BN + nq]);
            cpa16(sb, &Q[(size_t)(k0 + kr) * N + col0 + nq]);
            cpa16(sb + 64 * 4, &Q[(size_t)(k0 + kr) * N + col0 + nq + 64]);
            cpcommit();
        }
        mm_tile<BN>(As[kt & 1], Bs[kt & 1], acc, tx, ty);
    }

    // store Et tile
#pragma unroll
    for (int ih = 0; ih < 2; ih++) {
#pragma unroll
        for (int i2 = 0; i2 < 4; i2++) {
            int r = row0 + ih * 64 + ty * 4 + i2;
            int arr = ih * 4 + i2;
#pragma unroll
            for (int jh = 0; jh < 2; jh++) {
                float4 o;
                o.x = acc[arr][jh * 4 + 0];
                o.y = acc[arr][jh * 4 + 1];
                o.z = acc[arr][jh * 4 + 2];
                o.w = acc[arr][jh * 4 + 3];
                *(float4*)&E[(size_t)r * N + col0 + jh * 64 + tx * 4] = o;
            }
        }
    }

    // fused column max (over m) -> atomicMax on ordered ints
#pragma unroll
    for (int j = 0; j < 8; j++) {
        float m = acc[0][j];
#pragma unroll
        for (int i = 1; i < 8; i++) m = fmaxf(m, acc[i][j]);
        m = fmaxf(m, __shfl_xor_sync(0xffffffffu, m, 16));
        if ((tid & 31) < 16) {
            int col = col0 + (j >> 2) * 64 + tx * 4 + (j & 3);
            atomicMax(&g_colmax[b * N + col], f2o(m));
        }
    }
}

// ---------------------------------------------------------------------------
// exp + partial column sums (in place): E[m][n] = exp(Et[m][n] - max[n])
// ---------------------------------------------------------------------------
__global__ __launch_bounds__(256) void expsum_kernel()
{
    int b = blockIdx.z;
    int mz = blockIdx.y;
    int n = blockIdx.x * 256 + threadIdx.x;
    float* E = g_E + (size_t)b * N * N;
    float mx = o2f(g_colmax[b * N + n]);
    float s = 0.f;
    int m0 = mz * (N / MSPLIT);
    for (int m = m0; m < m0 + N / MSPLIT; m += 8) {
        float v[8];
#pragma unroll
        for (int i = 0; i < 8; i++) v[i] = E[(size_t)(m + i) * N + n];
#pragma unroll
        for (int i = 0; i < 8; i++) {
            float p = __expf(v[i] - mx);
            E[(size_t)(m + i) * N + n] = p;
            s += p;
        }
    }
    g_sumpart[mz][b * N + n] = s;
}

__global__ void reduce_kernel()
{
    int i = blockIdx.x * 256 + threadIdx.x;
    float s = 0.f;
#pragma unroll
    for (int p = 0; p < MSPLIT; p++) s += g_sumpart[p][i];
    g_colinv[i] = 1.f / s;
}

// ---------------------------------------------------------------------------
// Out: out[b,c,n] = gamma * inv[n] * (sum_m V[b,c,m] * P[b,m,n]) + x[b,c,n]
// A = V (transpose via LDG+STS), B = P (natural, cp.async), double-buffered.
// ---------------------------------------------------------------------------
__global__ __launch_bounds__(256) void out_kernel(
    const float* __restrict__ x, const float* __restrict__ gamma,
    float* __restrict__ out)
{
    int b = blockIdx.z;
    const float* V = g_v + (size_t)b * C * N;
    const float* P = g_E + (size_t)b * N * N;
    int row0 = blockIdx.y * BM;   // channel c
    int col0 = blockIdx.x * BN;   // position n

    __shared__ __align__(16) float As[2][BK * ASTR];
    __shared__ __align__(16) float Bs[2][BK * BN];

    int tid = threadIdx.x;
    int tx = tid & 15, ty = tid >> 4;

    int ar = tid >> 2;            // 0..63
    int ak = (tid & 3) * 4;
    int bkr = tid >> 4;
    int bn  = (tid & 15) * 4;

    float acc[8][8];
#pragma unroll
    for (int i = 0; i < 8; i++)
#pragma unroll
        for (int j = 0; j < 8; j++) acc[i][j] = 0.f;

    const int KT = N / BK;   // 256
    float4 av0, av1;

    // prologue
    {
        av0 = *(const float4*)&V[(size_t)(row0 + ar) * N + ak];
        av1 = *(const float4*)&V[(size_t)(row0 + ar + 64) * N + ak];
        unsigned s = smem_u32(&Bs[0][bkr * BN + bn]);
        cpa16(s, &P[(size_t)bkr * N + col0 + bn]);
        cpa16(s + 64 * 4, &P[(size_t)bkr * N + col0 + bn + 64]);
        cpcommit();
        float* A = As[0];
        A[(ak + 0) * ASTR + ar] = av0.x; A[(ak + 1) * ASTR + ar] = av0.y;
        A[(ak + 2) * ASTR + ar] = av0.z; A[(ak + 3) * ASTR + ar] = av0.w;
        A[(ak + 0) * ASTR + ar + 64] = av1.x; A[(ak + 1) * ASTR + ar + 64] = av1.y;
        A[(ak + 2) * ASTR + ar + 64] = av1.z; A[(ak + 3) * ASTR + ar + 64] = av1.w;
    }

    for (int kt = 0; kt < KT; kt++) {
        cpwait0();
        __syncthreads();
        int nk = kt + 1;
        if (nk < KT) {
            int m0 = nk * BK;
            unsigned s = smem_u32(&Bs[nk & 1][bkr * BN + bn]);
            cpa16(s, &P[(size_t)(m0 + bkr) * N + col0 + bn]);
            cpa16(s + 64 * 4, &P[(size_t)(m0 + bkr) * N + col0 + bn + 64]);
            cpcommit();
            av0 = *(const float4*)&V[(size_t)(row0 + ar) * N + m0 + ak];
            av1 = *(const float4*)&V[(size_t)(row0 + ar + 64) * N + m0 + ak];
        }
        mm_tile<ASTR>(As[kt & 1], Bs[kt & 1], acc, tx, ty);
        if (nk < KT) {
            float* A = As[nk & 1];
            A[(ak + 0) * ASTR + ar] = av0.x; A[(ak + 1) * ASTR + ar] = av0.y;
            A[(ak + 2) * ASTR + ar] = av0.z; A[(ak + 3) * ASTR + ar] = av0.w;
            A[(ak + 0) * ASTR + ar + 64] = av1.x; A[(ak + 1) * ASTR + ar + 64] = av1.y;
            A[(ak + 2) * ASTR + ar + 64] = av1.z; A[(ak + 3) * ASTR + ar + 64] = av1.w;
        }
    }

    float g = gamma[0];
    float4 iv0 = *(const float4*)&g_colinv[b * N + col0 + tx * 4];
    float4 iv1 = *(const float4*)&g_colinv[b * N + col0 + tx * 4 + 64];
    float inv[8] = {iv0.x, iv0.y, iv0.z, iv0.w, iv1.x, iv1.y, iv1.z, iv1.w};

#pragma unroll
    for (int ih = 0; ih < 2; ih++) {
#pragma unroll
        for (int i2 = 0; i2 < 4; i2++) {
            int r = row0 + ih * 64 + ty * 4 + i2;
            int arr = ih * 4 + i2;
#pragma unroll
            for (int jh = 0; jh < 2; jh++) {
                int cn = col0 + jh * 64 + tx * 4;
                size_t base = (size_t)b * C * N + (size_t)r * N + cn;
                float4 xv = *(const float4*)&x[base];
                float4 o;
                o.x = g * acc[arr][jh * 4 + 0] * inv[jh * 4 + 0] + xv.x;
                o.y = g * acc[arr][jh * 4 + 1] * inv[jh * 4 + 1] + xv.y;
                o.z = g * acc[arr][jh * 4 + 2] * inv[jh * 4 + 2] + xv.z;
                o.w = g * acc[arr][jh * 4 + 3] * inv[jh * 4 + 3] + xv.w;
                *(float4*)&out[base] = o;
            }
        }
    }
}

// ---------------------------------------------------------------------------
extern "C" void kernel_launch(void* const* d_in, const int* in_sizes, int n_in,
                              void* d_out, int out_size)
{
    const float* x     = (const float*)d_in[0];
    const float* Wq    = (const float*)d_in[1];
    const float* bq    = (const float*)d_in[2];
    const float* Wk    = (const float*)d_in[3];
    const float* bk    = (const float*)d_in[4];
    const float* Wv    = (const float*)d_in[5];
    const float* bv    = (const float*)d_in[6];
    const float* gamma = (const float*)d_in[7];
    float* out = (float*)d_out;

    dim3 blk(256);

    init_kernel<<<(BATCH * N) / 256, 256>>>();

    proj_kernel<<<dim3(N / BN, 1, BATCH), blk>>>(Wq, bq, x, 0, CQ);
    proj_kernel<<<dim3(N / BN, 1, BATCH), blk>>>(Wk, bk, x, 1, CQ);
    proj_kernel<<<dim3(N / BN, C / BM, BATCH), blk>>>(Wv, bv, x, 2, C);

    energy_kernel<<<dim3(N / BN, N / BM, BATCH), blk>>>();

    expsum_kernel<<<dim3(N / 256, MSPLIT, BATCH), 256>>>();
    reduce_kernel<<<(BATCH * N) / 256, 256>>>();

    out_kernel<<<dim3(N / BN, C / BM, BATCH), blk>>>(x, gamma, out);
}

// round 4
// speedup vs baseline: 3.8138x; 2.7964x over previous
#include <cuda_runtime.h>
#include <cstdint>

#define BATCH 4
#define C 512
#define CQ 64
#define NPOS 4096

#define BM 128
#define BN 128
#define BKF 16
#define ASTR 132

// ---------------- scratch (device globals) ----------------------------------
__device__ float g_qT[(size_t)BATCH * NPOS * CQ];   // [b][n][o]  tf32-rounded
__device__ float g_kT[(size_t)BATCH * NPOS * CQ];   // [b][m][o]  tf32-rounded
__device__ float g_v [(size_t)BATCH * C * NPOS];    // [b][c][m]  tf32-rounded
__device__ float g_P [(size_t)BATCH * NPOS * NPOS]; // [b][n][m] = tf32(exp(E))
__device__ float g_sum[BATCH * NPOS];
__device__ float g_inv[BATCH * NPOS];

// ---------------- helpers ----------------------------------------------------
__device__ __forceinline__ unsigned smem_u32(const void* p) {
    return (unsigned)__cvta_generic_to_shared(p);
}
__device__ __forceinline__ void cpa16(unsigned s, const float* g) {
    asm volatile("cp.async.cg.shared.global [%0], [%1], 16;\n" :: "r"(s), "l"(g));
}
__device__ __forceinline__ void cpcommit() { asm volatile("cp.async.commit_group;\n" ::); }
template <int n>
__device__ __forceinline__ void cpwait() { asm volatile("cp.async.wait_group %0;\n" :: "n"(n)); }

__device__ __forceinline__ float tf32r(float x) {
    uint32_t u;
    asm("cvt.rna.tf32.f32 %0, %1;" : "=r"(u) : "f"(x));
    return __uint_as_float(u);
}

__device__ __forceinline__ void ldm_x4(uint32_t* r, uint32_t addr) {
    asm volatile("ldmatrix.sync.aligned.m8n8.x4.shared.b16 {%0,%1,%2,%3}, [%4];"
        : "=r"(r[0]), "=r"(r[1]), "=r"(r[2]), "=r"(r[3]) : "r"(addr));
}
__device__ __forceinline__ void mma_tf32(float* d, const uint32_t* a, const uint32_t* b) {
    asm volatile("mma.sync.aligned.m16n8k8.row.col.f32.tf32.tf32.f32 "
        "{%0,%1,%2,%3}, {%4,%5,%6,%7}, {%8,%9}, {%0,%1,%2,%3};"
        : "+f"(d[0]), "+f"(d[1]), "+f"(d[2]), "+f"(d[3])
        : "r"(a[0]), "r"(a[1]), "r"(a[2]), "r"(a[3]), "r"(b[0]), "r"(b[1]));
}

// ---------------------------------------------------------------------------
__global__ void zero_kernel() {
    int i = blockIdx.x * 256 + threadIdx.x;
    g_sum[i] = 0.f;
}
__global__ void inv_kernel() {
    int i = blockIdx.x * 256 + threadIdx.x;
    g_inv[i] = 1.f / g_sum[i];
}

// ---------------------------------------------------------------------------
// FFMA proj for q/k (M=64). Writes TRANSPOSED + tf32-rounded: qT[n][o].
// ---------------------------------------------------------------------------
__global__ __launch_bounds__(256) void proj_qk_kernel(
    const float* __restrict__ W, const float* __restrict__ bias,
    const float* __restrict__ x, int which)
{
    float* Yg = (which == 0) ? g_qT : g_kT;
    int b = blockIdx.z;
    const float* X = x + (size_t)b * C * NPOS;
    int col0 = blockIdx.x * BN;
    const int M = CQ;

    __shared__ __align__(16) float As[2][BKF * ASTR];
    __shared__ __align__(16) float Bs[2][BKF * BN];

    int tid = threadIdx.x;
    int tx = tid & 15, ty = tid >> 4;
    int ar = tid >> 2, ak = (tid & 3) * 4;
    int bkr = tid >> 4, bn = (tid & 15) * 4;

    float acc[4][8];
#pragma unroll
    for (int i = 0; i < 4; i++)
#pragma unroll
        for (int j = 0; j < 8; j++) acc[i][j] = 0.f;

    const int KT = C / BKF;
    float4 av0;
    float4 zero4 = make_float4(0.f, 0.f, 0.f, 0.f);

    {
        av0 = (ar < M) ? *(const float4*)&W[(size_t)ar * C + ak] : zero4;
        unsigned s = smem_u32(&Bs[0][bkr * BN + bn]);
        cpa16(s, &X[(size_t)bkr * NPOS + col0 + bn]);
        cpa16(s + 64 * 4, &X[(size_t)bkr * NPOS + col0 + bn + 64]);
        cpcommit();
        float* A = As[0];
        A[(ak + 0) * ASTR + ar] = av0.x; A[(ak + 1) * ASTR + ar] = av0.y;
        A[(ak + 2) * ASTR + ar] = av0.z; A[(ak + 3) * ASTR + ar] = av0.w;
    }

    for (int kt = 0; kt < KT; kt++) {
        cpwait<0>();
        __syncthreads();
        int nk = kt + 1;
        if (nk < KT) {
            int k0 = nk * BKF;
            unsigned s = smem_u32(&Bs[nk & 1][bkr * BN + bn]);
            cpa16(s, &X[(size_t)(k0 + bkr) * NPOS + col0 + bn]);
            cpa16(s + 64 * 4, &X[(size_t)(k0 + bkr) * NPOS + col0 + bn + 64]);
            cpcommit();
            av0 = (ar < M) ? *(const float4*)&W[(size_t)ar * C + k0 + ak] : zero4;
        }
        const float* Af = As[kt & 1];
        const float* Bf = Bs[kt & 1];
#pragma unroll
        for (int kk = 0; kk < BKF; kk++) {
            float4 a0 = *(const float4*)(Af + kk * ASTR + ty * 4);
            float4 b0 = *(const float4*)(Bf + kk * BN + tx * 4);
            float4 b1 = *(const float4*)(Bf + kk * BN + tx * 4 + 64);
            float a[4] = {a0.x, a0.y, a0.z, a0.w};
            float bb[8] = {b0.x, b0.y, b0.z, b0.w, b1.x, b1.y, b1.z, b1.w};
#pragma unroll
            for (int i = 0; i < 4; i++)
#pragma unroll
                for (int j = 0; j < 8; j++)
                    acc[i][j] += a[i] * bb[j];
        }
        __syncthreads();
        if (nk < KT) {
            float* A = As[nk & 1];
            A[(ak + 0) * ASTR + ar] = av0.x; A[(ak + 1) * ASTR + ar] = av0.y;
            A[(ak + 2) * ASTR + ar] = av0.z; A[(ak + 3) * ASTR + ar] = av0.w;
        }
    }

    float* Y = Yg + (size_t)b * NPOS * CQ;
#pragma unroll
    for (int i2 = 0; i2 < 4; i2++) {
        int r = ty * 4 + i2;
        if (r >= M) continue;
        float bv_ = bias[r];
#pragma unroll
        for (int jh = 0; jh < 2; jh++) {
#pragma unroll
            for (int j2 = 0; j2 < 4; j2++) {
                int n = col0 + jh * 64 + tx * 4 + j2;
                Y[(size_t)n * CQ + r] = tf32r(acc[i2][jh * 4 + j2] + bv_);
            }
        }
    }
}

// ---------------------------------------------------------------------------
// FFMA proj for V (M=512): v[c][n] tf32-rounded.
// ---------------------------------------------------------------------------
__global__ __launch_bounds__(256) void proj_v_kernel(
    const float* __restrict__ W, const float* __restrict__ bias,
    const float* __restrict__ x)
{
    int b = blockIdx.z;
    const float* X = x + (size_t)b * C * NPOS;
    float* Y = g_v + (size_t)b * C * NPOS;
    int row0 = blockIdx.y * BM;
    int col0 = blockIdx.x * BN;

    __shared__ __align__(16) float As[2][BKF * ASTR];
    __shared__ __align__(16) float Bs[2][BKF * BN];

    int tid = threadIdx.x;
    int tx = tid & 15, ty = tid >> 4;
    int ar = tid >> 2, ak = (tid & 3) * 4;
    int bkr = tid >> 4, bn = (tid & 15) * 4;

    float acc[8][8];
#pragma unroll
    for (int i = 0; i < 8; i++)
#pragma unroll
        for (int j = 0; j < 8; j++) acc[i][j] = 0.f;

    const int KT = C / BKF;
    float4 av0, av1;

    {
        av0 = *(const float4*)&W[(size_t)(row0 + ar) * C + ak];
        av1 = *(const float4*)&W[(size_t)(row0 + ar + 64) * C + ak];
        unsigned s = smem_u32(&Bs[0][bkr * BN + bn]);
        cpa16(s, &X[(size_t)bkr * NPOS + col0 + bn]);
        cpa16(s + 64 * 4, &X[(size_t)bkr * NPOS + col0 + bn + 64]);
        cpcommit();
        float* A = As[0];
        A[(ak + 0) * ASTR + ar] = av0.x; A[(ak + 1) * ASTR + ar] = av0.y;
        A[(ak + 2) * ASTR + ar] = av0.z; A[(ak + 3) * ASTR + ar] = av0.w;
        A[(ak + 0) * ASTR + ar + 64] = av1.x; A[(ak + 1) * ASTR + ar + 64] = av1.y;
        A[(ak + 2) * ASTR + ar + 64] = av1.z; A[(ak + 3) * ASTR + ar + 64] = av1.w;
    }

    for (int kt = 0; kt < KT; kt++) {
        cpwait<0>();
        __syncthreads();
        int nk = kt + 1;
        if (nk < KT) {
            int k0 = nk * BKF;
            unsigned s = smem_u32(&Bs[nk & 1][bkr * BN + bn]);
            cpa16(s, &X[(size_t)(k0 + bkr) * NPOS + col0 + bn]);
            cpa16(s + 64 * 4, &X[(size_t)(k0 + bkr) * NPOS + col0 + bn + 64]);
            cpcommit();
            av0 = *(const float4*)&W[(size_t)(row0 + ar) * C + k0 + ak];
            av1 = *(const float4*)&W[(size_t)(row0 + ar + 64) * C + k0 + ak];
        }
        const float* Af = As[kt & 1];
        const float* Bf = Bs[kt & 1];
#pragma unroll
        for (int kk = 0; kk < BKF; kk++) {
            float4 a0 = *(const float4*)(Af + kk * ASTR + ty * 4);
            float4 a1 = *(const float4*)(Af + kk * ASTR + ty * 4 + 64);
            float4 b0 = *(const float4*)(Bf + kk * BN + tx * 4);
            float4 b1 = *(const float4*)(Bf + kk * BN + tx * 4 + 64);
            float a[8] = {a0.x, a0.y, a0.z, a0.w, a1.x, a1.y, a1.z, a1.w};
            float bb[8] = {b0.x, b0.y, b0.z, b0.w, b1.x, b1.y, b1.z, b1.w};
#pragma unroll
            for (int i = 0; i < 8; i++)
#pragma unroll
                for (int j = 0; j < 8; j++)
                    acc[i][j] += a[i] * bb[j];
        }
        __syncthreads();
        if (nk < KT) {
            float* A = As[nk & 1];
            A[(ak + 0) * ASTR + ar] = av0.x; A[(ak + 1) * ASTR + ar] = av0.y;
            A[(ak + 2) * ASTR + ar] = av0.z; A[(ak + 3) * ASTR + ar] = av0.w;
            A[(ak + 0) * ASTR + ar + 64] = av1.x; A[(ak + 1) * ASTR + ar + 64] = av1.y;
            A[(ak + 2) * ASTR + ar + 64] = av1.z; A[(ak + 3) * ASTR + ar + 64] = av1.w;
        }
    }

#pragma unroll
    for (int ih = 0; ih < 2; ih++) {
#pragma unroll
        for (int i2 = 0; i2 < 4; i2++) {
            int r = row0 + ih * 64 + ty * 4 + i2;
            float bv_ = bias[r];
            int arr = ih * 4 + i2;
#pragma unroll
            for (int jh = 0; jh < 2; jh++) {
                float4 o;
                o.x = tf32r(acc[arr][jh * 4 + 0] + bv_);
                o.y = tf32r(acc[arr][jh * 4 + 1] + bv_);
                o.z = tf32r(acc[arr][jh * 4 + 2] + bv_);
                o.w = tf32r(acc[arr][jh * 4 + 3] + bv_);
                *(float4*)&Y[(size_t)r * NPOS + col0 + jh * 64 + tx * 4] = o;
            }
        }
    }
}

// ---------------------------------------------------------------------------
// Energy (mma.sync tf32): D[n][m] = sum_o qT[n][o]*kT[m][o].
// Epilogue: P = tf32(exp(D)), row sums via atomics (max-free softmax).
// 256 thr = 8 warps (2 x-rows of n × 4 cols of m). Dyn smem 65536.
// ---------------------------------------------------------------------------
__global__ __launch_bounds__(256) void energy_kernel()
{
    extern __shared__ __align__(16) float smem[];
    uint32_t sA = smem_u32(smem);
    uint32_t sB = sA + 32768;

    int tid = threadIdx.x, lane = tid & 31, wid = tid >> 5;
    int warp_mi = wid >> 2;        // n-dim: 0..1 (64 rows each)
    int warp_ni = wid & 3;         // m-dim: 0..3 (32 cols each)
    int b = blockIdx.z;
    int m0 = blockIdx.x * 128, n0 = blockIdx.y * 128;

    const float* Aq = g_qT + ((size_t)b * NPOS + n0) * CQ;
    const float* Bk = g_kT + ((size_t)b * NPOS + m0) * CQ;

    // load 128x64 tiles, XOR-swizzled chunks (16 chunks/row)
#pragma unroll
    for (int i = 0; i < 8; i++) {
        int idx = i * 256 + tid;
        int r = idx >> 4, c = idx & 15;
        int cs = c ^ (r & 7);
        cpa16(sA + r * 256 + cs * 16, Aq + (size_t)r * CQ + c * 4);
        cpa16(sB + r * 256 + cs * 16, Bk + (size_t)r * CQ + c * 4);
    }
    cpcommit();
    cpwait<0>();
    __syncthreads();

    float acc[4][4][4];
#pragma unroll
    for (int i = 0; i < 4; i++)
#pragma unroll
        for (int j = 0; j < 4; j++)
#pragma unroll
            for (int k = 0; k < 4; k++) acc[i][j][k] = 0.f;

    int a_row_b = warp_mi * 64 + (lane & 15);
    int a_cadd = lane >> 4;
    int b_row_b = warp_ni * 32 + (lane & 7) + ((lane >> 4) << 3);
    int b_cadd = (lane >> 3) & 1;

#pragma unroll
    for (int ks = 0; ks < 8; ks++) {
        int kc = ks * 2;
        uint32_t a[4][4];
#pragma unroll
        for (int mi = 0; mi < 4; mi++) {
            int row = a_row_b + mi * 16;
            int cs = (kc + a_cadd) ^ (row & 7);
            ldm_x4(a[mi], sA + row * 256 + cs * 16);
        }
        uint32_t bf[2][4];
#pragma unroll
        for (int j2 = 0; j2 < 2; j2++) {
            int row = b_row_b + j2 * 16;
            int cs = (kc + b_cadd) ^ (row & 7);
            ldm_x4(bf[j2], sB + row * 256 + cs * 16);
        }
#pragma unroll
        for (int mi = 0; mi < 4; mi++)
#pragma unroll
            for (int ni = 0; ni < 4; ni++)
                mma_tf32(acc[mi][ni], a[mi], &bf[ni >> 1][(ni & 1) * 2]);
    }

    // ---- epilogue: exp, row sums, store P
    int g = lane >> 2, tq = lane & 3;
    float* Pout = g_P + (size_t)b * NPOS * NPOS;
    float* SUM = g_sum + b * NPOS;

#pragma unroll
    for (int mi = 0; mi < 4; mi++) {
        int r0 = n0 + warp_mi * 64 + mi * 16 + g;
        int r1 = r0 + 8;
        float s0 = 0.f, s1 = 0.f;
#pragma unroll
        for (int ni = 0; ni < 4; ni++) {
            float e0 = __expf(acc[mi][ni][0]);
            float e1 = __expf(acc[mi][ni][1]);
            float e2 = __expf(acc[mi][ni][2]);
            float e3 = __expf(acc[mi][ni][3]);
            s0 += e0 + e1;
            s1 += e2 + e3;
            int col = m0 + warp_ni * 32 + ni * 8 + 2 * tq;
            float2 v0 = make_float2(tf32r(e0), tf32r(e1));
            float2 v1 = make_float2(tf32r(e2), tf32r(e3));
            *(float2*)&Pout[(size_t)r0 * NPOS + col] = v0;
            *(float2*)&Pout[(size_t)r1 * NPOS + col] = v1;
        }
        s0 += __shfl_xor_sync(0xffffffffu, s0, 1);
        s0 += __shfl_xor_sync(0xffffffffu, s0, 2);
        s1 += __shfl_xor_sync(0xffffffffu, s1, 1);
        s1 += __shfl_xor_sync(0xffffffffu, s1, 2);
        if (tq == 0) {
            atomicAdd(&SUM[r0], s0);
            atomicAdd(&SUM[r1], s1);
        }
    }
}

// ---------------------------------------------------------------------------
// Out (mma.sync tf32, 3-stage cp.async): D[c][n] = sum_m V[c][m]*P[n][m]
// Epilogue: out = gamma*inv[n]*D + x. 256 thr. Dyn smem 98304.
// ---------------------------------------------------------------------------
__global__ __launch_bounds__(256) void out_kernel(
    const float* __restrict__ x, const float* __restrict__ gamma,
    float* __restrict__ out)
{
    extern __shared__ __align__(16) float smem[];
    uint32_t sbase = smem_u32(smem);

    int tid = threadIdx.x, lane = tid & 31, wid = tid >> 5;
    int warp_mi = wid >> 2;        // c-dim
    int warp_ni = wid & 3;         // n-dim
    int b = blockIdx.z;
    int n0 = blockIdx.x * 128, c0 = blockIdx.y * 128;

    const float* V = g_v + ((size_t)b * C + c0) * NPOS;
    const float* P = g_P + ((size_t)b * NPOS + n0) * NPOS;

    const int KT = NPOS / 32;      // 128

    auto load_stage = [&](int s, int kt) {
        int mb = kt * 32;
        uint32_t st = sbase + s * 32768;
#pragma unroll
        for (int i = 0; i < 4; i++) {
            int idx = i * 256 + tid;
            int r = idx >> 3, c = idx & 7;
            int cs = c ^ (r & 7);
            cpa16(st + r * 128 + cs * 16, V + (size_t)r * NPOS + mb + c * 4);
            cpa16(st + 16384 + r * 128 + cs * 16, P + (size_t)r * NPOS + mb + c * 4);
        }
        cpcommit();
    };

    load_stage(0, 0);
    load_stage(1, 1);

    float acc[4][4][4];
#pragma unroll
    for (int i = 0; i < 4; i++)
#pragma unroll
        for (int j = 0; j < 4; j++)
#pragma unroll
            for (int k = 0; k < 4; k++) acc[i][j][k] = 0.f;

    int a_row_b = warp_mi * 64 + (lane & 15);
    int a_cadd = lane >> 4;
    int b_row_b = warp_ni * 32 + (lane & 7) + ((lane >> 4) << 3);
    int b_cadd = (lane >> 3) & 1;

    for (int kt = 0; kt < KT; kt++) {
        if (kt >= KT - 1) cpwait<0>(); else cpwait<1>();
        __syncthreads();
        if (kt + 2 < KT) load_stage((kt + 2) % 3, kt + 2);

        uint32_t sA = sbase + (kt % 3) * 32768;
        uint32_t sB = sA + 16384;
#pragma unroll
        for (int ks = 0; ks < 4; ks++) {
            int kc = ks * 2;
            uint32_t a[4][4];
#pragma unroll
            for (int mi = 0; mi < 4; mi++) {
                int row = a_row_b + mi * 16;
                int cs = (kc + a_cadd) ^ (row & 7);
                ldm_x4(a[mi], sA + row * 128 + cs * 16);
            }
            uint32_t bf[2][4];
#pragma unroll
            for (int j2 = 0; j2 < 2; j2++) {
                int row = b_row_b + j2 * 16;
                int cs = (kc + b_cadd) ^ (row & 7);
                ldm_x4(bf[j2], sB + row * 128 + cs * 16);
            }
#pragma unroll
            for (int mi = 0; mi < 4; mi++)
#pragma unroll
                for (int ni = 0; ni < 4; ni++)
                    mma_tf32(acc[mi][ni], a[mi], &bf[ni >> 1][(ni & 1) * 2]);
        }
    }

    // ---- epilogue
    int g = lane >> 2, tq = lane & 3;
    float gm = gamma[0];
    float2 iv[4];
#pragma unroll
    for (int ni = 0; ni < 4; ni++) {
        int ncol = n0 + warp_ni * 32 + ni * 8 + 2 * tq;
        iv[ni] = *(const float2*)&g_inv[b * NPOS + ncol];
    }

#pragma unroll
    for (int mi = 0; mi < 4; mi++) {
        int c_r0 = c0 + warp_mi * 64 + mi * 16 + g;
        int c_r1 = c_r0 + 8;
#pragma unroll
        for (int ni = 0; ni < 4; ni++) {
            int ncol = n0 + warp_ni * 32 + ni * 8 + 2 * tq;
            size_t off0 = ((size_t)b * C + c_r0) * NPOS + ncol;
            size_t off1 = ((size_t)b * C + c_r1) * NPOS + ncol;
            float2 xv0 = *(const float2*)&x[off0];
            float2 xv1 = *(const float2*)&x[off1];
            float2 o0, o1;
            o0.x = gm * iv[ni].x * acc[mi][ni][0] + xv0.x;
            o0.y = gm * iv[ni].y * acc[mi][ni][1] + xv0.y;
            o1.x = gm * iv[ni].x * acc[mi][ni][2] + xv1.x;
            o1.y = gm * iv[ni].y * acc[mi][ni][3] + xv1.y;
            *(float2*)&out[off0] = o0;
            *(float2*)&out[off1] = o1;
        }
    }
}

// ---------------------------------------------------------------------------
extern "C" void kernel_launch(void* const* d_in, const int* in_sizes, int n_in,
                              void* d_out, int out_size)
{
    const float* x     = (const float*)d_in[0];
    const float* Wq    = (const float*)d_in[1];
    const float* bq    = (const float*)d_in[2];
    const float* Wk    = (const float*)d_in[3];
    const float* bk    = (const float*)d_in[4];
    const float* Wv    = (const float*)d_in[5];
    const float* bv    = (const float*)d_in[6];
    const float* gamma = (const float*)d_in[7];
    float* out = (float*)d_out;

    cudaFuncSetAttribute(energy_kernel,
                         cudaFuncAttributeMaxDynamicSharedMemorySize, 65536);
    cudaFuncSetAttribute(out_kernel,
                         cudaFuncAttributeMaxDynamicSharedMemorySize, 98304);

    zero_kernel<<<(BATCH * NPOS) / 256, 256>>>();

    proj_qk_kernel<<<dim3(NPOS / BN, 1, BATCH), 256>>>(Wq, bq, x, 0);
    proj_qk_kernel<<<dim3(NPOS / BN, 1, BATCH), 256>>>(Wk, bk, x, 1);
    proj_v_kernel<<<dim3(NPOS / BN, C / BM, BATCH), 256>>>(Wv, bv, x);

    energy_kernel<<<dim3(NPOS / 128, NPOS / 128, BATCH), 256, 65536>>>();
    inv_kernel<<<(BATCH * NPOS) / 256, 256>>>();

    out_kernel<<<dim3(NPOS / 128, C / 128, BATCH), 256, 98304>>>(x, gamma, out);
}

// round 6
// speedup vs baseline: 4.5405x; 1.1906x over previous
#include <cuda_runtime.h>
#include <cstdint>

#define BATCH 4
#define C 512
#define CQ 64
#define NPOS 4096

#define BN 128
#define BKF 16
#define ASTR 132

// ---------------- scratch (device globals) ----------------------------------
__device__ float    g_qT[(size_t)BATCH * NPOS * CQ];    // [b][n][o] tf32
__device__ float    g_kT[(size_t)BATCH * NPOS * CQ];    // [b][m][o] tf32
__device__ uint16_t g_v [(size_t)BATCH * C * NPOS];     // [b][c][m] bf16
__device__ uint16_t g_P [(size_t)BATCH * NPOS * NPOS];  // [b][n][m] bf16 exp(E)
__device__ uint16_t g_xb[(size_t)BATCH * C * NPOS];     // [b][c][n] bf16
__device__ float    g_sum[BATCH * NPOS];
__device__ float    g_inv[BATCH * NPOS];

// ---------------- helpers ----------------------------------------------------
__device__ __forceinline__ unsigned smem_u32(const void* p) {
    return (unsigned)__cvta_generic_to_shared(p);
}
__device__ __forceinline__ void cpa16(unsigned s, const void* g) {
    asm volatile("cp.async.cg.shared.global [%0], [%1], 16;\n" :: "r"(s), "l"(g));
}
__device__ __forceinline__ void cpcommit() { asm volatile("cp.async.commit_group;\n" ::); }
template <int n>
__device__ __forceinline__ void cpwait() { asm volatile("cp.async.wait_group %0;\n" :: "n"(n)); }

__device__ __forceinline__ float tf32r(float x) {
    uint32_t u;
    asm("cvt.rna.tf32.f32 %0, %1;" : "=r"(u) : "f"(x));
    return __uint_as_float(u);
}
__device__ __forceinline__ uint32_t bpack(float lo, float hi) {
    uint32_t u;
    asm("cvt.rn.bf16x2.f32 %0, %1, %2;" : "=r"(u) : "f"(hi), "f"(lo));
    return u;
}
__device__ __forceinline__ void ldm_x4(uint32_t* r, uint32_t addr) {
    asm volatile("ldmatrix.sync.aligned.m8n8.x4.shared.b16 {%0,%1,%2,%3}, [%4];"
        : "=r"(r[0]), "=r"(r[1]), "=r"(r[2]), "=r"(r[3]) : "r"(addr));
}
__device__ __forceinline__ void ldm_x4_t(uint32_t* r, uint32_t addr) {
    asm volatile("ldmatrix.sync.aligned.m8n8.x4.trans.shared.b16 {%0,%1,%2,%3}, [%4];"
        : "=r"(r[0]), "=r"(r[1]), "=r"(r[2]), "=r"(r[3]) : "r"(addr));
}
__device__ __forceinline__ void mma_tf32(float* d, const uint32_t* a, const uint32_t* b) {
    asm volatile("mma.sync.aligned.m16n8k8.row.col.f32.tf32.tf32.f32 "
        "{%0,%1,%2,%3}, {%4,%5,%6,%7}, {%8,%9}, {%0,%1,%2,%3};"
        : "+f"(d[0]), "+f"(d[1]), "+f"(d[2]), "+f"(d[3])
        : "r"(a[0]), "r"(a[1]), "r"(a[2]), "r"(a[3]), "r"(b[0]), "r"(b[1]));
}
__device__ __forceinline__ void mma_bf16(float* d, const uint32_t* a, const uint32_t* b) {
    asm volatile("mma.sync.aligned.m16n8k16.row.col.f32.bf16.bf16.f32 "
        "{%0,%1,%2,%3}, {%4,%5,%6,%7}, {%8,%9}, {%0,%1,%2,%3};"
        : "+f"(d[0]), "+f"(d[1]), "+f"(d[2]), "+f"(d[3])
        : "r"(a[0]), "r"(a[1]), "r"(a[2]), "r"(a[3]), "r"(b[0]), "r"(b[1]));
}

// single extern shared symbol, consistent type across all kernels
extern __shared__ __align__(16) char smem[];

// ---------------------------------------------------------------------------
__global__ void zero_kernel() {
    int i = blockIdx.x * 256 + threadIdx.x;
    g_sum[i] = 0.f;
}
__global__ void inv_kernel() {
    int i = blockIdx.x * 256 + threadIdx.x;
    g_inv[i] = 1.f / g_sum[i];
}
// x (fp32) -> g_xb (bf16)
__global__ void cvt_x_kernel(const float* __restrict__ x) {
    size_t i = (size_t)(blockIdx.x * 256 + threadIdx.x) * 4;
    float4 v = *(const float4*)&x[i];
    uint2 o;
    o.x = bpack(v.x, v.y);
    o.y = bpack(v.z, v.w);
    *(uint2*)&g_xb[i] = o;
}

// ---------------------------------------------------------------------------
// FFMA proj for q/k (M=64). Writes TRANSPOSED + tf32-rounded: qT[n][o].
// ---------------------------------------------------------------------------
__global__ __launch_bounds__(256) void proj_qk_kernel(
    const float* __restrict__ W, const float* __restrict__ bias,
    const float* __restrict__ x, int which)
{
    float* Yg = (which == 0) ? g_qT : g_kT;
    int b = blockIdx.z;
    const float* X = x + (size_t)b * C * NPOS;
    int col0 = blockIdx.x * BN;
    const int M = CQ;

    __shared__ __align__(16) float As[2][BKF * ASTR];
    __shared__ __align__(16) float Bs[2][BKF * BN];

    int tid = threadIdx.x;
    int tx = tid & 15, ty = tid >> 4;
    int ar = tid >> 2, ak = (tid & 3) * 4;
    int bkr = tid >> 4, bn = (tid & 15) * 4;

    float acc[4][8];
#pragma unroll
    for (int i = 0; i < 4; i++)
#pragma unroll
        for (int j = 0; j < 8; j++) acc[i][j] = 0.f;

    const int KT = C / BKF;
    float4 av0;
    float4 zero4 = make_float4(0.f, 0.f, 0.f, 0.f);

    {
        av0 = (ar < M) ? *(const float4*)&W[(size_t)ar * C + ak] : zero4;
        unsigned s = smem_u32(&Bs[0][bkr * BN + bn]);
        cpa16(s, &X[(size_t)bkr * NPOS + col0 + bn]);
        cpa16(s + 64 * 4, &X[(size_t)bkr * NPOS + col0 + bn + 64]);
        cpcommit();
        float* A = As[0];
        A[(ak + 0) * ASTR + ar] = av0.x; A[(ak + 1) * ASTR + ar] = av0.y;
        A[(ak + 2) * ASTR + ar] = av0.z; A[(ak + 3) * ASTR + ar] = av0.w;
    }

    for (int kt = 0; kt < KT; kt++) {
        cpwait<0>();
        __syncthreads();
        int nk = kt + 1;
        if (nk < KT) {
            int k0 = nk * BKF;
            unsigned s = smem_u32(&Bs[nk & 1][bkr * BN + bn]);
            cpa16(s, &X[(size_t)(k0 + bkr) * NPOS + col0 + bn]);
            cpa16(s + 64 * 4, &X[(size_t)(k0 + bkr) * NPOS + col0 + bn + 64]);
            cpcommit();
            av0 = (ar < M) ? *(const float4*)&W[(size_t)ar * C + k0 + ak] : zero4;
        }
        const float* Af = As[kt & 1];
        const float* Bf = Bs[kt & 1];
#pragma unroll
        for (int kk = 0; kk < BKF; kk++) {
            float4 a0 = *(const float4*)(Af + kk * ASTR + ty * 4);
            float4 b0 = *(const float4*)(Bf + kk * BN + tx * 4);
            float4 b1 = *(const float4*)(Bf + kk * BN + tx * 4 + 64);
            float a[4] = {a0.x, a0.y, a0.z, a0.w};
            float bb[8] = {b0.x, b0.y, b0.z, b0.w, b1.x, b1.y, b1.z, b1.w};
#pragma unroll
            for (int i = 0; i < 4; i++)
#pragma unroll
                for (int j = 0; j < 8; j++)
                    acc[i][j] += a[i] * bb[j];
        }
        __syncthreads();
        if (nk < KT) {
            float* A = As[nk & 1];
            A[(ak + 0) * ASTR + ar] = av0.x; A[(ak + 1) * ASTR + ar] = av0.y;
            A[(ak + 2) * ASTR + ar] = av0.z; A[(ak + 3) * ASTR + ar] = av0.w;
        }
    }

    float* Y = Yg + (size_t)b * NPOS * CQ;
#pragma unroll
    for (int i2 = 0; i2 < 4; i2++) {
        int r = ty * 4 + i2;
        if (r >= M) continue;
        float bv_ = bias[r];
#pragma unroll
        for (int jh = 0; jh < 2; jh++) {
#pragma unroll
            for (int j2 = 0; j2 < 4; j2++) {
                int n = col0 + jh * 64 + tx * 4 + j2;
                Y[(size_t)n * CQ + r] = tf32r(acc[i2][jh * 4 + j2] + bv_);
            }
        }
    }
}

// ---------------------------------------------------------------------------
// proj_v (bf16 mma): V[c][n] = sum_k Wv[c][k] * xb[k][n] + bv[c], store bf16.
// A = Wv (LDG fp32 -> cvt -> STS, double-buffered regs), B = xb (cp.async).
// B fragments via ldmatrix.trans on k-major tiles. 256 thr, dyn smem 65536.
// ---------------------------------------------------------------------------
__global__ __launch_bounds__(256) void proj_v_kernel(
    const float* __restrict__ W, const float* __restrict__ bias)
{
    uint32_t sbase = smem_u32(smem);

    int tid = threadIdx.x, lane = tid & 31, wid = tid >> 5;
    int warp_mi = wid >> 2;        // c-dim (2 x 64)
    int warp_ni = wid & 3;         // n-dim (4 x 32)
    int b = blockIdx.z;
    int n0 = blockIdx.x * 128, c0 = blockIdx.y * 128;

    const uint16_t* X = g_xb + (size_t)b * C * NPOS;

    const int KT = C / 64;         // 8

    float aw[4][8];
    auto ldgA = [&](int kt) {
#pragma unroll
        for (int i = 0; i < 4; i++) {
            int idx = tid + i * 256;
            int r = idx >> 3, c = idx & 7;
            const float* src = W + (size_t)(c0 + r) * C + kt * 64 + c * 8;
            float4 v0 = *(const float4*)src;
            float4 v1 = *(const float4*)(src + 4);
            aw[i][0] = v0.x; aw[i][1] = v0.y; aw[i][2] = v0.z; aw[i][3] = v0.w;
            aw[i][4] = v1.x; aw[i][5] = v1.y; aw[i][6] = v1.z; aw[i][7] = v1.w;
        }
    };
    auto stsA = [&](int s) {
#pragma unroll
        for (int i = 0; i < 4; i++) {
            int idx = tid + i * 256;
            int r = idx >> 3, c = idx & 7;
            int cs = c ^ (r & 7);
            uint4 o;
            o.x = bpack(aw[i][0], aw[i][1]);
            o.y = bpack(aw[i][2], aw[i][3]);
            o.z = bpack(aw[i][4], aw[i][5]);
            o.w = bpack(aw[i][6], aw[i][7]);
            *(uint4*)(smem + s * 32768 + r * 128 + cs * 16) = o;
        }
    };
    auto cpaB = [&](int kt, int s) {
#pragma unroll
        for (int i = 0; i < 4; i++) {
            int idx = tid + i * 256;
            int r = idx >> 4, c = idx & 15;
            int cs = (c & 8) | ((c & 7) ^ (r & 7));
            cpa16(sbase + s * 32768 + 16384 + r * 256 + cs * 16,
                  X + (size_t)(kt * 64 + r) * NPOS + n0 + c * 8);
        }
        cpcommit();
    };

    float acc[4][4][4];
#pragma unroll
    for (int i = 0; i < 4; i++)
#pragma unroll
        for (int j = 0; j < 4; j++)
#pragma unroll
            for (int k = 0; k < 4; k++) acc[i][j][k] = 0.f;

    ldgA(0);
    cpaB(0, 0);
    stsA(0);

    for (int kt = 0; kt < KT; kt++) {
        cpwait<0>();
        __syncthreads();
        if (kt + 1 < KT) {
            cpaB(kt + 1, (kt + 1) & 1);
            ldgA(kt + 1);
        }
        uint32_t sA = sbase + (kt & 1) * 32768;
        uint32_t sB = sA + 16384;
#pragma unroll
        for (int ks = 0; ks < 4; ks++) {
            uint32_t a[4][4];
#pragma unroll
            for (int mi = 0; mi < 4; mi++) {
                int row = warp_mi * 64 + mi * 16 + (lane & 15);
                int ch = ks * 2 + (lane >> 4);
                int cs = ch ^ (row & 7);
                ldm_x4(a[mi], sA + row * 128 + cs * 16);
            }
            uint32_t bf[2][4];
#pragma unroll
            for (int nb = 0; nb < 2; nb++) {
                int krow = ks * 16 + (lane & 7) + ((lane >> 3) & 1) * 8;
                int nch = warp_ni * 4 + nb * 2 + (lane >> 4);
                int cs = (nch & 8) | ((nch & 7) ^ (krow & 7));
                ldm_x4_t(bf[nb], sB + krow * 256 + cs * 16);
            }
#pragma unroll
            for (int mi = 0; mi < 4; mi++)
#pragma unroll
                for (int ni = 0; ni < 4; ni++)
                    mma_bf16(acc[mi][ni], a[mi], &bf[ni >> 1][(ni & 1) * 2]);
        }
        if (kt + 1 < KT) stsA((kt + 1) & 1);
    }

    // epilogue: + bias, cvt bf16, store [c][n]
    int g = lane >> 2, tq = lane & 3;
    uint16_t* Vout = g_v + (size_t)b * C * NPOS;
#pragma unroll
    for (int mi = 0; mi < 4; mi++) {
        int c_r0 = c0 + warp_mi * 64 + mi * 16 + g;
        int c_r1 = c_r0 + 8;
        float bv0 = bias[c_r0], bv1 = bias[c_r1];
#pragma unroll
        for (int ni = 0; ni < 4; ni++) {
            int ncol = n0 + warp_ni * 32 + ni * 8 + 2 * tq;
            *(uint32_t*)&Vout[(size_t)c_r0 * NPOS + ncol] =
                bpack(acc[mi][ni][0] + bv0, acc[mi][ni][1] + bv0);
            *(uint32_t*)&Vout[(size_t)c_r1 * NPOS + ncol] =
                bpack(acc[mi][ni][2] + bv1, acc[mi][ni][3] + bv1);
        }
    }
}

// ---------------------------------------------------------------------------
// Energy (mma.sync tf32): D[n][m] = sum_o qT[n][o]*kT[m][o].
// Epilogue: P = bf16(exp(D)), row sums via atomics (max-free softmax).
// ---------------------------------------------------------------------------
__global__ __launch_bounds__(256) void energy_kernel()
{
    uint32_t sA = smem_u32(smem);
    uint32_t sB = sA + 32768;

    int tid = threadIdx.x, lane = tid & 31, wid = tid >> 5;
    int warp_mi = wid >> 2;
    int warp_ni = wid & 3;
    int b = blockIdx.z;
    int m0 = blockIdx.x * 128, n0 = blockIdx.y * 128;

    const float* Aq = g_qT + ((size_t)b * NPOS + n0) * CQ;
    const float* Bk = g_kT + ((size_t)b * NPOS + m0) * CQ;

#pragma unroll
    for (int i = 0; i < 8; i++) {
        int idx = i * 256 + tid;
        int r = idx >> 4, c = idx & 15;
        int cs = c ^ (r & 7);
        cpa16(sA + r * 256 + cs * 16, Aq + (size_t)r * CQ + c * 4);
        cpa16(sB + r * 256 + cs * 16, Bk + (size_t)r * CQ + c * 4);
    }
    cpcommit();
    cpwait<0>();
    __syncthreads();

    float acc[4][4][4];
#pragma unroll
    for (int i = 0; i < 4; i++)
#pragma unroll
        for (int j = 0; j < 4; j++)
#pragma unroll
            for (int k = 0; k < 4; k++) acc[i][j][k] = 0.f;

    int a_row_b = warp_mi * 64 + (lane & 15);
    int a_cadd = lane >> 4;
    int b_row_b = warp_ni * 32 + (lane & 7) + ((lane >> 4) << 3);
    int b_cadd = (lane >> 3) & 1;

#pragma unroll
    for (int ks = 0; ks < 8; ks++) {
        int kc = ks * 2;
        uint32_t a[4][4];
#pragma unroll
        for (int mi = 0; mi < 4; mi++) {
            int row = a_row_b + mi * 16;
            int cs = (kc + a_cadd) ^ (row & 7);
            ldm_x4(a[mi], sA + row * 256 + cs * 16);
        }
        uint32_t bf[2][4];
#pragma unroll
        for (int j2 = 0; j2 < 2; j2++) {
            int row = b_row_b + j2 * 16;
            int cs = (kc + b_cadd) ^ (row & 7);
            ldm_x4(bf[j2], sB + row * 256 + cs * 16);
        }
#pragma unroll
        for (int mi = 0; mi < 4; mi++)
#pragma unroll
            for (int ni = 0; ni < 4; ni++)
                mma_tf32(acc[mi][ni], a[mi], &bf[ni >> 1][(ni & 1) * 2]);
    }

    int g = lane >> 2, tq = lane & 3;
    uint16_t* Pout = g_P + (size_t)b * NPOS * NPOS;
    float* SUM = g_sum + b * NPOS;

#pragma unroll
    for (int mi = 0; mi < 4; mi++) {
        int r0 = n0 + warp_mi * 64 + mi * 16 + g;
        int r1 = r0 + 8;
        float s0 = 0.f, s1 = 0.f;
#pragma unroll
        for (int ni = 0; ni < 4; ni++) {
            float e0 = __expf(acc[mi][ni][0]);
            float e1 = __expf(acc[mi][ni][1]);
            float e2 = __expf(acc[mi][ni][2]);
            float e3 = __expf(acc[mi][ni][3]);
            s0 += e0 + e1;
            s1 += e2 + e3;
            int col = m0 + warp_ni * 32 + ni * 8 + 2 * tq;
            *(uint32_t*)&Pout[(size_t)r0 * NPOS + col] = bpack(e0, e1);
            *(uint32_t*)&Pout[(size_t)r1 * NPOS + col] = bpack(e2, e3);
        }
        s0 += __shfl_xor_sync(0xffffffffu, s0, 1);
        s0 += __shfl_xor_sync(0xffffffffu, s0, 2);
        s1 += __shfl_xor_sync(0xffffffffu, s1, 1);
        s1 += __shfl_xor_sync(0xffffffffu, s1, 2);
        if (tq == 0) {
            atomicAdd(&SUM[r0], s0);
            atomicAdd(&SUM[r1], s1);
        }
    }
}

// ---------------------------------------------------------------------------
// Out (bf16 mma, 3-stage cp.async): D[c][n] = sum_m V[c][m]*P[n][m]
// Epilogue: out = gamma*inv[n]*D + x. 256 thr, dyn smem 98304.
// ---------------------------------------------------------------------------
__global__ __launch_bounds__(256) void out_kernel(
    const float* __restrict__ x, const float* __restrict__ gamma,
    float* __restrict__ out)
{
    uint32_t sbase = smem_u32(smem);

    int tid = threadIdx.x, lane = tid & 31, wid = tid >> 5;
    int warp_mi = wid >> 2;
    int warp_ni = wid & 3;
    int b = blockIdx.z;
    int n0 = blockIdx.x * 128, c0 = blockIdx.y * 128;

    const uint16_t* V = g_v + ((size_t)b * C + c0) * NPOS;
    const uint16_t* P = g_P + ((size_t)b * NPOS + n0) * NPOS;

    const int KT = NPOS / 64;      // 64

    auto load_stage = [&](int s, int kt) {
        int mb = kt * 64;
        uint32_t st = sbase + s * 32768;
#pragma unroll
        for (int i = 0; i < 4; i++) {
            int idx = i * 256 + tid;
            int r = idx >> 3, c = idx & 7;
            int cs = c ^ (r & 7);
            cpa16(st + r * 128 + cs * 16, V + (size_t)r * NPOS + mb + c * 8);
            cpa16(st + 16384 + r * 128 + cs * 16, P + (size_t)r * NPOS + mb + c * 8);
        }
        cpcommit();
    };

    load_stage(0, 0);
    load_stage(1, 1);

    float acc[4][4][4];
#pragma unroll
    for (int i = 0; i < 4; i++)
#pragma unroll
        for (int j = 0; j < 4; j++)
#pragma unroll
            for (int k = 0; k < 4; k++) acc[i][j][k] = 0.f;

    int a_row_b = warp_mi * 64 + (lane & 15);
    int a_cadd = lane >> 4;
    int b_row_b = warp_ni * 32 + (lane & 7) + ((lane >> 4) << 3);
    int b_cadd = (lane >> 3) & 1;

    for (int kt = 0; kt < KT; kt++) {
        if (kt >= KT - 1) cpwait<0>(); else cpwait<1>();
        __syncthreads();
        if (kt + 2 < KT) load_stage((kt + 2) % 3, kt + 2);

        uint32_t sA = sbase + (kt % 3) * 32768;
        uint32_t sB = sA + 16384;
#pragma unroll
        for (int ks = 0; ks < 4; ks++) {
            int kc = ks * 2;
            uint32_t a[4][4];
#pragma unroll
            for (int mi = 0; mi < 4; mi++) {
                int row = a_row_b + mi * 16;
                int cs = (kc + a_cadd) ^ (row & 7);
                ldm_x4(a[mi], sA + row * 128 + cs * 16);
            }
            uint32_t bf[2][4];
#pragma unroll
            for (int j2 = 0; j2 < 2; j2++) {
                int row = b_row_b + j2 * 16;
                int cs = (kc + b_cadd) ^ (row & 7);
                ldm_x4(bf[j2], sB + row * 128 + cs * 16);
            }
#pragma unroll
            for (int mi = 0; mi < 4; mi++)
#pragma unroll
                for (int ni = 0; ni < 4; ni++)
                    mma_bf16(acc[mi][ni], a[mi], &bf[ni >> 1][(ni & 1) * 2]);
        }
    }

    int g = lane >> 2, tq = lane & 3;
    float gm = gamma[0];
    float2 iv[4];
#pragma unroll
    for (int ni = 0; ni < 4; ni++) {
        int ncol = n0 + warp_ni * 32 + ni * 8 + 2 * tq;
        iv[ni] = *(const float2*)&g_inv[b * NPOS + ncol];
    }

#pragma unroll
    for (int mi = 0; mi < 4; mi++) {
        int c_r0 = c0 + warp_mi * 64 + mi * 16 + g;
        int c_r1 = c_r0 + 8;
#pragma unroll
        for (int ni = 0; ni < 4; ni++) {
            int ncol = n0 + warp_ni * 32 + ni * 8 + 2 * tq;
            size_t off0 = ((size_t)b * C + c_r0) * NPOS + ncol;
            size_t off1 = ((size_t)b * C + c_r1) * NPOS + ncol;
            float2 xv0 = *(const float2*)&x[off0];
            float2 xv1 = *(const float2*)&x[off1];
            float2 o0, o1;
            o0.x = gm * iv[ni].x * acc[mi][ni][0] + xv0.x;
            o0.y = gm * iv[ni].y * acc[mi][ni][1] + xv0.y;
            o1.x = gm * iv[ni].x * acc[mi][ni][2] + xv1.x;
            o1.y = gm * iv[ni].y * acc[mi][ni][3] + xv1.y;
            *(float2*)&out[off0] = o0;
            *(float2*)&out[off1] = o1;
        }
    }
}

// ---------------------------------------------------------------------------
extern "C" void kernel_launch(void* const* d_in, const int* in_sizes, int n_in,
                              void* d_out, int out_size)
{
    const float* x     = (const float*)d_in[0];
    const float* Wq    = (const float*)d_in[1];
    const float* bq    = (const float*)d_in[2];
    const float* Wk    = (const float*)d_in[3];
    const float* bk    = (const float*)d_in[4];
    const float* Wv    = (const float*)d_in[5];
    const float* bv    = (const float*)d_in[6];
    const float* gamma = (const float*)d_in[7];
    float* out = (float*)d_out;

    cudaFuncSetAttribute(energy_kernel,
                         cudaFuncAttributeMaxDynamicSharedMemorySize, 65536);
    cudaFuncSetAttribute(out_kernel,
                         cudaFuncAttributeMaxDynamicSharedMemorySize, 98304);
    cudaFuncSetAttribute(proj_v_kernel,
                         cudaFuncAttributeMaxDynamicSharedMemorySize, 65536);

    zero_kernel<<<(BATCH * NPOS) / 256, 256>>>();
    cvt_x_kernel<<<(int)((size_t)BATCH * C * NPOS / 4 / 256), 256>>>(x);

    proj_qk_kernel<<<dim3(NPOS / BN, 1, BATCH), 256>>>(Wq, bq, x, 0);
    proj_qk_kernel<<<dim3(NPOS / BN, 1, BATCH), 256>>>(Wk, bk, x, 1);
    proj_v_kernel<<<dim3(NPOS / 128, C / 128, BATCH), 256, 65536>>>(Wv, bv);

    energy_kernel<<<dim3(NPOS / 128, NPOS / 128, BATCH), 256, 65536>>>();
    inv_kernel<<<(BATCH * NPOS) / 256, 256>>>();

    out_kernel<<<dim3(NPOS / 128, C / 128, BATCH), 256, 98304>>>(x, gamma, out);
}

// round 7
// speedup vs baseline: 8.2495x; 1.8169x over previous
#include <cuda_runtime.h>
#include <cstdint>

#define BATCH 4
#define C 512
#define CQ 64
#define NPOS 4096

// ---------------- scratch (device globals) ----------------------------------
__device__ uint16_t g_qbT[(size_t)BATCH * NPOS * CQ];   // [b][n][o] bf16
__device__ uint16_t g_kbT[(size_t)BATCH * NPOS * CQ];   // [b][m][o] bf16
__device__ uint16_t g_v [(size_t)BATCH * C * NPOS];     // [b][c][m] bf16
__device__ uint16_t g_P [(size_t)BATCH * NPOS * NPOS];  // [b][n][m] bf16 exp(E)
__device__ uint16_t g_xb[(size_t)BATCH * C * NPOS];     // [b][c][n] bf16
__device__ float    g_sum[BATCH * NPOS];
__device__ float    g_inv[BATCH * NPOS];

// ---------------- helpers ----------------------------------------------------
__device__ __forceinline__ unsigned smem_u32(const void* p) {
    return (unsigned)__cvta_generic_to_shared(p);
}
__device__ __forceinline__ void cpa16(unsigned s, const void* g) {
    asm volatile("cp.async.cg.shared.global [%0], [%1], 16;\n" :: "r"(s), "l"(g));
}
__device__ __forceinline__ void cpcommit() { asm volatile("cp.async.commit_group;\n" ::); }
template <int n>
__device__ __forceinline__ void cpwait() { asm volatile("cp.async.wait_group %0;\n" :: "n"(n)); }

__device__ __forceinline__ uint32_t bpack(float lo, float hi) {
    uint32_t u;
    asm("cvt.rn.bf16x2.f32 %0, %1, %2;" : "=r"(u) : "f"(hi), "f"(lo));
    return u;
}
__device__ __forceinline__ uint16_t bf16of(float x) {
    return (uint16_t)(bpack(x, x) & 0xffffu);
}
__device__ __forceinline__ void ldm_x4(uint32_t* r, uint32_t addr) {
    asm volatile("ldmatrix.sync.aligned.m8n8.x4.shared.b16 {%0,%1,%2,%3}, [%4];"
        : "=r"(r[0]), "=r"(r[1]), "=r"(r[2]), "=r"(r[3]) : "r"(addr));
}
__device__ __forceinline__ void ldm_x4_t(uint32_t* r, uint32_t addr) {
    asm volatile("ldmatrix.sync.aligned.m8n8.x4.trans.shared.b16 {%0,%1,%2,%3}, [%4];"
        : "=r"(r[0]), "=r"(r[1]), "=r"(r[2]), "=r"(r[3]) : "r"(addr));
}
__device__ __forceinline__ void mma_bf16(float* d, const uint32_t* a, const uint32_t* b) {
    asm volatile("mma.sync.aligned.m16n8k16.row.col.f32.bf16.bf16.f32 "
        "{%0,%1,%2,%3}, {%4,%5,%6,%7}, {%8,%9}, {%0,%1,%2,%3};"
        : "+f"(d[0]), "+f"(d[1]), "+f"(d[2]), "+f"(d[3])
        : "r"(a[0]), "r"(a[1]), "r"(a[2]), "r"(a[3]), "r"(b[0]), "r"(b[1]));
}

extern __shared__ __align__(16) char smem[];

// ---------------------------------------------------------------------------
__global__ void zero_kernel() {
    int i = blockIdx.x * 256 + threadIdx.x;
    g_sum[i] = 0.f;
}
__global__ void inv_kernel() {
    int i = blockIdx.x * 256 + threadIdx.x;
    g_inv[i] = 1.f / g_sum[i];
}
__global__ void cvt_x_kernel(const float* __restrict__ x) {
    size_t i = (size_t)(blockIdx.x * 256 + threadIdx.x) * 4;
    float4 v = *(const float4*)&x[i];
    uint2 o;
    o.x = bpack(v.x, v.y);
    o.y = bpack(v.z, v.w);
    *(uint2*)&g_xb[i] = o;
}

// ---------------------------------------------------------------------------
// Fused q/k projection (bf16 mma): D[r][n] = sum_k Wqk[r][k] * xb[k][n] + b[r]
// rows 0-63 = Wq, rows 64-127 = Wk. Epilogue stores TRANSPOSED bf16 [n][o].
// 256 thr, dyn smem 65536. Same structure as proj_v.
// ---------------------------------------------------------------------------
__global__ __launch_bounds__(256) void proj_qk_kernel(
    const float* __restrict__ Wq, const float* __restrict__ bq,
    const float* __restrict__ Wk, const float* __restrict__ bk)
{
    uint32_t sbase = smem_u32(smem);

    int tid = threadIdx.x, lane = tid & 31, wid = tid >> 5;
    int warp_mi = wid >> 2;        // r-dim: 0 = q rows, 1 = k rows
    int warp_ni = wid & 3;         // n-dim (4 x 32)
    int b = blockIdx.z;
    int n0 = blockIdx.x * 128;

    const uint16_t* X = g_xb + (size_t)b * C * NPOS;
    const int KT = C / 64;         // 8

    float aw[4][8];
    auto ldgA = [&](int kt) {
#pragma unroll
        for (int i = 0; i < 4; i++) {
            int idx = tid + i * 256;
            int r = idx >> 3, c = idx & 7;
            const float* src = (r < 64)
                ? Wq + (size_t)r * C + kt * 64 + c * 8
                : Wk + (size_t)(r - 64) * C + kt * 64 + c * 8;
            float4 v0 = *(const float4*)src;
            float4 v1 = *(const float4*)(src + 4);
            aw[i][0] = v0.x; aw[i][1] = v0.y; aw[i][2] = v0.z; aw[i][3] = v0.w;
            aw[i][4] = v1.x; aw[i][5] = v1.y; aw[i][6] = v1.z; aw[i][7] = v1.w;
        }
    };
    auto stsA = [&](int s) {
#pragma unroll
        for (int i = 0; i < 4; i++) {
            int idx = tid + i * 256;
            int r = idx >> 3, c = idx & 7;
            int cs = c ^ (r & 7);
            uint4 o;
            o.x = bpack(aw[i][0], aw[i][1]);
            o.y = bpack(aw[i][2], aw[i][3]);
            o.z = bpack(aw[i][4], aw[i][5]);
            o.w = bpack(aw[i][6], aw[i][7]);
            *(uint4*)(smem + s * 32768 + r * 128 + cs * 16) = o;
        }
    };
    auto cpaB = [&](int kt, int s) {
#pragma unroll
        for (int i = 0; i < 4; i++) {
            int idx = tid + i * 256;
            int r = idx >> 4, c = idx & 15;
            int cs = (c & 8) | ((c & 7) ^ (r & 7));
            cpa16(sbase + s * 32768 + 16384 + r * 256 + cs * 16,
                  X + (size_t)(kt * 64 + r) * NPOS + n0 + c * 8);
        }
        cpcommit();
    };

    float acc[4][4][4];
#pragma unroll
    for (int i = 0; i < 4; i++)
#pragma unroll
        for (int j = 0; j < 4; j++)
#pragma unroll
            for (int k = 0; k < 4; k++) acc[i][j][k] = 0.f;

    ldgA(0);
    cpaB(0, 0);
    stsA(0);

    for (int kt = 0; kt < KT; kt++) {
        cpwait<0>();
        __syncthreads();
        if (kt + 1 < KT) {
            cpaB(kt + 1, (kt + 1) & 1);
            ldgA(kt + 1);
        }
        uint32_t sA = sbase + (kt & 1) * 32768;
        uint32_t sB = sA + 16384;
#pragma unroll
        for (int ks = 0; ks < 4; ks++) {
            uint32_t a[4][4];
#pragma unroll
            for (int mi = 0; mi < 4; mi++) {
                int row = warp_mi * 64 + mi * 16 + (lane & 15);
                int ch = ks * 2 + (lane >> 4);
                int cs = ch ^ (row & 7);
                ldm_x4(a[mi], sA + row * 128 + cs * 16);
            }
            uint32_t bf[2][4];
#pragma unroll
            for (int nb = 0; nb < 2; nb++) {
                int krow = ks * 16 + (lane & 7) + ((lane >> 3) & 1) * 8;
                int nch = warp_ni * 4 + nb * 2 + (lane >> 4);
                int cs = (nch & 8) | ((nch & 7) ^ (krow & 7));
                ldm_x4_t(bf[nb], sB + krow * 256 + cs * 16);
            }
#pragma unroll
            for (int mi = 0; mi < 4; mi++)
#pragma unroll
                for (int ni = 0; ni < 4; ni++)
                    mma_bf16(acc[mi][ni], a[mi], &bf[ni >> 1][(ni & 1) * 2]);
        }
        if (kt + 1 < KT) stsA((kt + 1) & 1);
    }

    // epilogue: + bias, transposed bf16 store. warp_mi 0 -> q, 1 -> k.
    int g = lane >> 2, tq = lane & 3;
    uint16_t* Y = (warp_mi == 0 ? g_qbT : g_kbT) + (size_t)b * NPOS * CQ;
#pragma unroll
    for (int mi = 0; mi < 4; mi++) {
        int o0 = mi * 16 + g;          // 0..63 within q or k
        int o1 = o0 + 8;
        float bv0 = (warp_mi == 0) ? bq[o0] : bk[o0];
        float bv1 = (warp_mi == 0) ? bq[o1] : bk[o1];
#pragma unroll
        for (int ni = 0; ni < 4; ni++) {
            int ncol = n0 + warp_ni * 32 + ni * 8 + 2 * tq;
            Y[(size_t)ncol * CQ + o0]       = bf16of(acc[mi][ni][0] + bv0);
            Y[(size_t)(ncol + 1) * CQ + o0] = bf16of(acc[mi][ni][1] + bv0);
            Y[(size_t)ncol * CQ + o1]       = bf16of(acc[mi][ni][2] + bv1);
            Y[(size_t)(ncol + 1) * CQ + o1] = bf16of(acc[mi][ni][3] + bv1);
        }
    }
}

// ---------------------------------------------------------------------------
// proj_v (bf16 mma): V[c][n] = sum_k Wv[c][k] * xb[k][n] + bv[c], store bf16.
// ---------------------------------------------------------------------------
__global__ __launch_bounds__(256) void proj_v_kernel(
    const float* __restrict__ W, const float* __restrict__ bias)
{
    uint32_t sbase = smem_u32(smem);

    int tid = threadIdx.x, lane = tid & 31, wid = tid >> 5;
    int warp_mi = wid >> 2;
    int warp_ni = wid & 3;
    int b = blockIdx.z;
    int n0 = blockIdx.x * 128, c0 = blockIdx.y * 128;

    const uint16_t* X = g_xb + (size_t)b * C * NPOS;
    const int KT = C / 64;

    float aw[4][8];
    auto ldgA = [&](int kt) {
#pragma unroll
        for (int i = 0; i < 4; i++) {
            int idx = tid + i * 256;
            int r = idx >> 3, c = idx & 7;
            const float* src = W + (size_t)(c0 + r) * C + kt * 64 + c * 8;
            float4 v0 = *(const float4*)src;
            float4 v1 = *(const float4*)(src + 4);
            aw[i][0] = v0.x; aw[i][1] = v0.y; aw[i][2] = v0.z; aw[i][3] = v0.w;
            aw[i][4] = v1.x; aw[i][5] = v1.y; aw[i][6] = v1.z; aw[i][7] = v1.w;
        }
    };
    auto stsA = [&](int s) {
#pragma unroll
        for (int i = 0; i < 4; i++) {
            int idx = tid + i * 256;
            int r = idx >> 3, c = idx & 7;
            int cs = c ^ (r & 7);
            uint4 o;
            o.x = bpack(aw[i][0], aw[i][1]);
            o.y = bpack(aw[i][2], aw[i][3]);
            o.z = bpack(aw[i][4], aw[i][5]);
            o.w = bpack(aw[i][6], aw[i][7]);
            *(uint4*)(smem + s * 32768 + r * 128 + cs * 16) = o;
        }
    };
    auto cpaB = [&](int kt, int s) {
#pragma unroll
        for (int i = 0; i < 4; i++) {
            int idx = tid + i * 256;
            int r = idx >> 4, c = idx & 15;
            int cs = (c & 8) | ((c & 7) ^ (r & 7));
            cpa16(sbase + s * 32768 + 16384 + r * 256 + cs * 16,
                  X + (size_t)(kt * 64 + r) * NPOS + n0 + c * 8);
        }
        cpcommit();
    };

    float acc[4][4][4];
#pragma unroll
    for (int i = 0; i < 4; i++)
#pragma unroll
        for (int j = 0; j < 4; j++)
#pragma unroll
            for (int k = 0; k < 4; k++) acc[i][j][k] = 0.f;

    ldgA(0);
    cpaB(0, 0);
    stsA(0);

    for (int kt = 0; kt < KT; kt++) {
        cpwait<0>();
        __syncthreads();
        if (kt + 1 < KT) {
            cpaB(kt + 1, (kt + 1) & 1);
            ldgA(kt + 1);
        }
        uint32_t sA = sbase + (kt & 1) * 32768;
        uint32_t sB = sA + 16384;
#pragma unroll
        for (int ks = 0; ks < 4; ks++) {
            uint32_t a[4][4];
#pragma unroll
            for (int mi = 0; mi < 4; mi++) {
                int row = warp_mi * 64 + mi * 16 + (lane & 15);
                int ch = ks * 2 + (lane >> 4);
                int cs = ch ^ (row & 7);
                ldm_x4(a[mi], sA + row * 128 + cs * 16);
            }
            uint32_t bf[2][4];
#pragma unroll
            for (int nb = 0; nb < 2; nb++) {
                int krow = ks * 16 + (lane & 7) + ((lane >> 3) & 1) * 8;
                int nch = warp_ni * 4 + nb * 2 + (lane >> 4);
                int cs = (nch & 8) | ((nch & 7) ^ (krow & 7));
                ldm_x4_t(bf[nb], sB + krow * 256 + cs * 16);
            }
#pragma unroll
            for (int mi = 0; mi < 4; mi++)
#pragma unroll
                for (int ni = 0; ni < 4; ni++)
                    mma_bf16(acc[mi][ni], a[mi], &bf[ni >> 1][(ni & 1) * 2]);
        }
        if (kt + 1 < KT) stsA((kt + 1) & 1);
    }

    int g = lane >> 2, tq = lane & 3;
    uint16_t* Vout = g_v + (size_t)b * C * NPOS;
#pragma unroll
    for (int mi = 0; mi < 4; mi++) {
        int c_r0 = c0 + warp_mi * 64 + mi * 16 + g;
        int c_r1 = c_r0 + 8;
        float bv0 = bias[c_r0], bv1 = bias[c_r1];
#pragma unroll
        for (int ni = 0; ni < 4; ni++) {
            int ncol = n0 + warp_ni * 32 + ni * 8 + 2 * tq;
            *(uint32_t*)&Vout[(size_t)c_r0 * NPOS + ncol] =
                bpack(acc[mi][ni][0] + bv0, acc[mi][ni][1] + bv0);
            *(uint32_t*)&Vout[(size_t)c_r1 * NPOS + ncol] =
                bpack(acc[mi][ni][2] + bv1, acc[mi][ni][3] + bv1);
        }
    }
}

// ---------------------------------------------------------------------------
// Energy (bf16 mma): D[n][m] = sum_o qbT[n][o]*kbT[m][o], k=64 (4 ks steps).
// Epilogue: P = bf16(exp(D)), row sums via atomics (max-free softmax).
// 256 thr, dyn smem 32768.
// ---------------------------------------------------------------------------
__global__ __launch_bounds__(256) void energy_kernel()
{
    uint32_t sA = smem_u32(smem);
    uint32_t sB = sA + 16384;

    int tid = threadIdx.x, lane = tid & 31, wid = tid >> 5;
    int warp_mi = wid >> 2;        // n-dim (2 x 64)
    int warp_ni = wid & 3;         // m-dim (4 x 32)
    int b = blockIdx.z;
    int m0 = blockIdx.x * 128, n0 = blockIdx.y * 128;

    const uint16_t* Aq = g_qbT + ((size_t)b * NPOS + n0) * CQ;
    const uint16_t* Bk = g_kbT + ((size_t)b * NPOS + m0) * CQ;

#pragma unroll
    for (int i = 0; i < 4; i++) {
        int idx = i * 256 + tid;
        int r = idx >> 3, c = idx & 7;
        int cs = c ^ (r & 7);
        cpa16(sA + r * 128 + cs * 16, Aq + (size_t)r * CQ + c * 8);
        cpa16(sB + r * 128 + cs * 16, Bk + (size_t)r * CQ + c * 8);
    }
    cpcommit();
    cpwait<0>();
    __syncthreads();

    float acc[4][4][4];
#pragma unroll
    for (int i = 0; i < 4; i++)
#pragma unroll
        for (int j = 0; j < 4; j++)
#pragma unroll
            for (int k = 0; k < 4; k++) acc[i][j][k] = 0.f;

    int a_row_b = warp_mi * 64 + (lane & 15);
    int a_cadd = lane >> 4;
    int b_row_b = warp_ni * 32 + (lane & 7) + ((lane >> 4) << 3);
    int b_cadd = (lane >> 3) & 1;

#pragma unroll
    for (int ks = 0; ks < 4; ks++) {
        int kc = ks * 2;
        uint32_t a[4][4];
#pragma unroll
        for (int mi = 0; mi < 4; mi++) {
            int row = a_row_b + mi * 16;
            int cs = (kc + a_cadd) ^ (row & 7);
            ldm_x4(a[mi], sA + row * 128 + cs * 16);
        }
        uint32_t bf[2][4];
#pragma unroll
        for (int j2 = 0; j2 < 2; j2++) {
            int row = b_row_b + j2 * 16;
            int cs = (kc + b_cadd) ^ (row & 7);
            ldm_x4(bf[j2], sB + row * 128 + cs * 16);
        }
#pragma unroll
        for (int mi = 0; mi < 4; mi++)
#pragma unroll
            for (int ni = 0; ni < 4; ni++)
                mma_bf16(acc[mi][ni], a[mi], &bf[ni >> 1][(ni & 1) * 2]);
    }

    int g = lane >> 2, tq = lane & 3;
    uint16_t* Pout = g_P + (size_t)b * NPOS * NPOS;
    float* SUM = g_sum + b * NPOS;

#pragma unroll
    for (int mi = 0; mi < 4; mi++) {
        int r0 = n0 + warp_mi * 64 + mi * 16 + g;
        int r1 = r0 + 8;
        float s0 = 0.f, s1 = 0.f;
#pragma unroll
        for (int ni = 0; ni < 4; ni++) {
            float e0 = __expf(acc[mi][ni][0]);
            float e1 = __expf(acc[mi][ni][1]);
            float e2 = __expf(acc[mi][ni][2]);
            float e3 = __expf(acc[mi][ni][3]);
            s0 += e0 + e1;
            s1 += e2 + e3;
            int col = m0 + warp_ni * 32 + ni * 8 + 2 * tq;
            *(uint32_t*)&Pout[(size_t)r0 * NPOS + col] = bpack(e0, e1);
            *(uint32_t*)&Pout[(size_t)r1 * NPOS + col] = bpack(e2, e3);
        }
        s0 += __shfl_xor_sync(0xffffffffu, s0, 1);
        s0 += __shfl_xor_sync(0xffffffffu, s0, 2);
        s1 += __shfl_xor_sync(0xffffffffu, s1, 1);
        s1 += __shfl_xor_sync(0xffffffffu, s1, 2);
        if (tq == 0) {
            atomicAdd(&SUM[r0], s0);
            atomicAdd(&SUM[r1], s1);
        }
    }
}

// ---------------------------------------------------------------------------
// Out (bf16 mma, 256x128 tile, 3-stage): D[c][n] = sum_m V[c][m]*P[n][m]
// Epilogue: out = gamma*inv[n]*D + x. 256 thr, dyn smem 147456.
// ---------------------------------------------------------------------------
__global__ __launch_bounds__(256) void out_kernel(
    const float* __restrict__ x, const float* __restrict__ gamma,
    float* __restrict__ out)
{
    uint32_t sbase = smem_u32(smem);

    int tid = threadIdx.x, lane = tid & 31, wid = tid >> 5;
    int warp_mi = wid >> 1;        // c-dim (4 x 64)
    int warp_ni = wid & 1;         // n-dim (2 x 64)
    int b = blockIdx.z;
    int n0 = blockIdx.x * 128, c0 = blockIdx.y * 256;

    const uint16_t* V = g_v + ((size_t)b * C + c0) * NPOS;
    const uint16_t* P = g_P + ((size_t)b * NPOS + n0) * NPOS;

    const int KT = NPOS / 64;      // 64
    const int STG = 49152;         // 32KB A + 16KB B per stage

    auto load_stage = [&](int s, int kt) {
        int mb = kt * 64;
        uint32_t st = sbase + s * STG;
#pragma unroll
        for (int i = 0; i < 8; i++) {          // A: 256 rows x 128B
            int idx = i * 256 + tid;
            int r = idx >> 3, c = idx & 7;
            int cs = c ^ (r & 7);
            cpa16(st + r * 128 + cs * 16, V + (size_t)r * NPOS + mb + c * 8);
        }
#pragma unroll
        for (int i = 0; i < 4; i++) {          // B: 128 rows x 128B
            int idx = i * 256 + tid;
            int r = idx >> 3, c = idx & 7;
            int cs = c ^ (r & 7);
            cpa16(st + 32768 + r * 128 + cs * 16, P + (size_t)r * NPOS + mb + c * 8);
        }
        cpcommit();
    };

    load_stage(0, 0);
    load_stage(1, 1);

    float acc[4][8][4];
#pragma unroll
    for (int i = 0; i < 4; i++)
#pragma unroll
        for (int j = 0; j < 8; j++)
#pragma unroll
            for (int k = 0; k < 4; k++) acc[i][j][k] = 0.f;

    int a_row_b = warp_mi * 64 + (lane & 15);
    int a_cadd = lane >> 4;
    int b_row_b = warp_ni * 64 + (lane & 7) + ((lane >> 4) << 3);
    int b_cadd = (lane >> 3) & 1;

    for (int kt = 0; kt < KT; kt++) {
        if (kt >= KT - 1) cpwait<0>(); else cpwait<1>();
        __syncthreads();
        if (kt + 2 < KT) load_stage((kt + 2) % 3, kt + 2);

        uint32_t sA = sbase + (kt % 3) * STG;
        uint32_t sB = sA + 32768;
#pragma unroll
        for (int ks = 0; ks < 4; ks++) {
            int kc = ks * 2;
            uint32_t a[4][4];
#pragma unroll
            for (int mi = 0; mi < 4; mi++) {
                int row = a_row_b + mi * 16;
                int cs = (kc + a_cadd) ^ (row & 7);
                ldm_x4(a[mi], sA + row * 128 + cs * 16);
            }
            uint32_t bf[4][4];
#pragma unroll
            for (int j2 = 0; j2 < 4; j2++) {
                int row = b_row_b + j2 * 16;
                int cs = (kc + b_cadd) ^ (row & 7);
                ldm_x4(bf[j2], sB + row * 128 + cs * 16);
            }
#pragma unroll
            for (int mi = 0; mi < 4; mi++)
#pragma unroll
                for (int ni = 0; ni < 8; ni++)
                    mma_bf16(acc[mi][ni], a[mi], &bf[ni >> 1][(ni & 1) * 2]);
        }
    }

    int g = lane >> 2, tq = lane & 3;
    float gm = gamma[0];
    float2 iv[8];
#pragma unroll
    for (int ni = 0; ni < 8; ni++) {
        int ncol = n0 + warp_ni * 64 + ni * 8 + 2 * tq;
        iv[ni] = *(const float2*)&g_inv[b * NPOS + ncol];
    }

#pragma unroll
    for (int mi = 0; mi < 4; mi++) {
        int c_r0 = c0 + warp_mi * 64 + mi * 16 + g;
        int c_r1 = c_r0 + 8;
#pragma unroll
        for (int ni = 0; ni < 8; ni++) {
            int ncol = n0 + warp_ni * 64 + ni * 8 + 2 * tq;
            size_t off0 = ((size_t)b * C + c_r0) * NPOS + ncol;
            size_t off1 = ((size_t)b * C + c_r1) * NPOS + ncol;
            float2 xv0 = *(const float2*)&x[off0];
            float2 xv1 = *(const float2*)&x[off1];
            float2 o0, o1;
            o0.x = gm * iv[ni].x * acc[mi][ni][0] + xv0.x;
            o0.y = gm * iv[ni].y * acc[mi][ni][1] + xv0.y;
            o1.x = gm * iv[ni].x * acc[mi][ni][2] + xv1.x;
            o1.y = gm * iv[ni].y * acc[mi][ni][3] + xv1.y;
            *(float2*)&out[off0] = o0;
            *(float2*)&out[off1] = o1;
        }
    }
}

// ---------------------------------------------------------------------------
extern "C" void kernel_launch(void* const* d_in, const int* in_sizes, int n_in,
                              void* d_out, int out_size)
{
    const float* x     = (const float*)d_in[0];
    const float* Wq    = (const float*)d_in[1];
    const float* bq    = (const float*)d_in[2];
    const float* Wk    = (const float*)d_in[3];
    const float* bk    = (const float*)d_in[4];
    const float* Wv    = (const float*)d_in[5];
    const float* bv    = (const float*)d_in[6];
    const float* gamma = (const float*)d_in[7];
    float* out = (float*)d_out;

    cudaFuncSetAttribute(proj_qk_kernel,
                         cudaFuncAttributeMaxDynamicSharedMemorySize, 65536);
    cudaFuncSetAttribute(proj_v_kernel,
                         cudaFuncAttributeMaxDynamicSharedMemorySize, 65536);
    cudaFuncSetAttribute(energy_kernel,
                         cudaFuncAttributeMaxDynamicSharedMemorySize, 32768);
    cudaFuncSetAttribute(out_kernel,
                         cudaFuncAttributeMaxDynamicSharedMemorySize, 147456);

    zero_kernel<<<(BATCH * NPOS) / 256, 256>>>();
    cvt_x_kernel<<<(int)((size_t)BATCH * C * NPOS / 4 / 256), 256>>>(x);

    proj_qk_kernel<<<dim3(NPOS / 128, 1, BATCH), 256, 65536>>>(Wq, bq, Wk, bk);
    proj_v_kernel<<<dim3(NPOS / 128, C / 128, BATCH), 256, 65536>>>(Wv, bv);

    energy_kernel<<<dim3(NPOS / 128, NPOS / 128, BATCH), 256, 32768>>>();
    inv_kernel<<<(BATCH * NPOS) / 256, 256>>>();

    out_kernel<<<dim3(NPOS / 128, C / 256, BATCH), 256, 147456>>>(x, gamma, out);
}

// round 8
// speedup vs baseline: 8.3878x; 1.0168x over previous
#include <cuda_runtime.h>
#include <cstdint>

#define BATCH 4
#define C 512
#define CQ 64
#define NPOS 4096

#define LOG2E 1.4426950408889634f
#define PSHIFT 4.0f

// ---------------- scratch (device globals) ----------------------------------
__device__ uint16_t g_qbT[(size_t)BATCH * NPOS * CQ];   // [b][n][o] f16, pre-scaled by log2e
__device__ uint16_t g_kbT[(size_t)BATCH * NPOS * CQ];   // [b][m][o] f16
__device__ uint16_t g_v [(size_t)BATCH * C * NPOS];     // [b][c][m] f16
__device__ uint16_t g_P [(size_t)BATCH * NPOS * NPOS];  // [b][n][m] f16 2^(E*log2e-4)
__device__ uint16_t g_xb[(size_t)BATCH * C * NPOS];     // [b][c][n] f16
__device__ float    g_sum[BATCH * NPOS];
__device__ float    g_inv[BATCH * NPOS];

// ---------------- helpers ----------------------------------------------------
__device__ __forceinline__ unsigned smem_u32(const void* p) {
    return (unsigned)__cvta_generic_to_shared(p);
}
__device__ __forceinline__ void cpa16(unsigned s, const void* g) {
    asm volatile("cp.async.cg.shared.global [%0], [%1], 16;\n" :: "r"(s), "l"(g));
}
__device__ __forceinline__ void cpcommit() { asm volatile("cp.async.commit_group;\n" ::); }
template <int n>
__device__ __forceinline__ void cpwait() { asm volatile("cp.async.wait_group %0;\n" :: "n"(n)); }

// pack two f32 -> f16x2 (lo in low half)
__device__ __forceinline__ uint32_t hpack(float lo, float hi) {
    uint32_t u;
    asm("cvt.rn.f16x2.f32 %0, %1, %2;" : "=r"(u) : "f"(hi), "f"(lo));
    return u;
}
__device__ __forceinline__ uint16_t h16of(float x) {
    uint16_t h;
    asm("cvt.rn.f16.f32 %0, %1;" : "=h"(h) : "f"(x));
    return h;
}
__device__ __forceinline__ uint32_t ex2h2(uint32_t x) {
    uint32_t d;
    asm("ex2.approx.f16x2 %0, %1;" : "=r"(d) : "r"(x));
    return d;
}
__device__ __forceinline__ void ldm_x4(uint32_t* r, uint32_t addr) {
    asm volatile("ldmatrix.sync.aligned.m8n8.x4.shared.b16 {%0,%1,%2,%3}, [%4];"
        : "=r"(r[0]), "=r"(r[1]), "=r"(r[2]), "=r"(r[3]) : "r"(addr));
}
__device__ __forceinline__ void ldm_x4_t(uint32_t* r, uint32_t addr) {
    asm volatile("ldmatrix.sync.aligned.m8n8.x4.trans.shared.b16 {%0,%1,%2,%3}, [%4];"
        : "=r"(r[0]), "=r"(r[1]), "=r"(r[2]), "=r"(r[3]) : "r"(addr));
}
__device__ __forceinline__ void mma_h(float* d, const uint32_t* a, const uint32_t* b) {
    asm volatile("mma.sync.aligned.m16n8k16.row.col.f32.f16.f16.f32 "
        "{%0,%1,%2,%3}, {%4,%5,%6,%7}, {%8,%9}, {%0,%1,%2,%3};"
        : "+f"(d[0]), "+f"(d[1]), "+f"(d[2]), "+f"(d[3])
        : "r"(a[0]), "r"(a[1]), "r"(a[2]), "r"(a[3]), "r"(b[0]), "r"(b[1]));
}

extern __shared__ __align__(16) char smem[];

// ---------------------------------------------------------------------------
__global__ void zero_kernel() {
    int i = blockIdx.x * 256 + threadIdx.x;
    g_sum[i] = 0.f;
}
__global__ void inv_kernel() {
    int i = blockIdx.x * 256 + threadIdx.x;
    g_inv[i] = 1.f / g_sum[i];
}
__global__ void cvt_x_kernel(const float* __restrict__ x) {
    size_t i = (size_t)(blockIdx.x * 256 + threadIdx.x) * 4;
    float4 v = *(const float4*)&x[i];
    uint2 o;
    o.x = hpack(v.x, v.y);
    o.y = hpack(v.z, v.w);
    *(uint2*)&g_xb[i] = o;
}

// ---------------------------------------------------------------------------
// Fused q/k projection (f16 mma). rows 0-63 = Wq (scaled by log2e), 64-127 = Wk.
// Epilogue stores TRANSPOSED f16 [n][o].
// ---------------------------------------------------------------------------
__global__ __launch_bounds__(256) void proj_qk_kernel(
    const float* __restrict__ Wq, const float* __restrict__ bq,
    const float* __restrict__ Wk, const float* __restrict__ bk)
{
    uint32_t sbase = smem_u32(smem);

    int tid = threadIdx.x, lane = tid & 31, wid = tid >> 5;
    int warp_mi = wid >> 2;        // 0 = q rows, 1 = k rows
    int warp_ni = wid & 3;
    int b = blockIdx.z;
    int n0 = blockIdx.x * 128;

    const uint16_t* X = g_xb + (size_t)b * C * NPOS;
    const int KT = C / 64;

    float aw[4][8];
    auto ldgA = [&](int kt) {
#pragma unroll
        for (int i = 0; i < 4; i++) {
            int idx = tid + i * 256;
            int r = idx >> 3, c = idx & 7;
            const float* src = (r < 64)
                ? Wq + (size_t)r * C + kt * 64 + c * 8
                : Wk + (size_t)(r - 64) * C + kt * 64 + c * 8;
            float4 v0 = *(const float4*)src;
            float4 v1 = *(const float4*)(src + 4);
            aw[i][0] = v0.x; aw[i][1] = v0.y; aw[i][2] = v0.z; aw[i][3] = v0.w;
            aw[i][4] = v1.x; aw[i][5] = v1.y; aw[i][6] = v1.z; aw[i][7] = v1.w;
        }
    };
    auto stsA = [&](int s) {
#pragma unroll
        for (int i = 0; i < 4; i++) {
            int idx = tid + i * 256;
            int r = idx >> 3, c = idx & 7;
            int cs = c ^ (r & 7);
            uint4 o;
            o.x = hpack(aw[i][0], aw[i][1]);
            o.y = hpack(aw[i][2], aw[i][3]);
            o.z = hpack(aw[i][4], aw[i][5]);
            o.w = hpack(aw[i][6], aw[i][7]);
            *(uint4*)(smem + s * 32768 + r * 128 + cs * 16) = o;
        }
    };
    auto cpaB = [&](int kt, int s) {
#pragma unroll
        for (int i = 0; i < 4; i++) {
            int idx = tid + i * 256;
            int r = idx >> 4, c = idx & 15;
            int cs = (c & 8) | ((c & 7) ^ (r & 7));
            cpa16(sbase + s * 32768 + 16384 + r * 256 + cs * 16,
                  X + (size_t)(kt * 64 + r) * NPOS + n0 + c * 8);
        }
        cpcommit();
    };

    float acc[4][4][4];
#pragma unroll
    for (int i = 0; i < 4; i++)
#pragma unroll
        for (int j = 0; j < 4; j++)
#pragma unroll
            for (int k = 0; k < 4; k++) acc[i][j][k] = 0.f;

    ldgA(0);
    cpaB(0, 0);
    stsA(0);

    for (int kt = 0; kt < KT; kt++) {
        cpwait<0>();
        __syncthreads();
        if (kt + 1 < KT) {
            cpaB(kt + 1, (kt + 1) & 1);
            ldgA(kt + 1);
        }
        uint32_t sA = sbase + (kt & 1) * 32768;
        uint32_t sB = sA + 16384;
#pragma unroll
        for (int ks = 0; ks < 4; ks++) {
            uint32_t a[4][4];
#pragma unroll
            for (int mi = 0; mi < 4; mi++) {
                int row = warp_mi * 64 + mi * 16 + (lane & 15);
                int ch = ks * 2 + (lane >> 4);
                int cs = ch ^ (row & 7);
                ldm_x4(a[mi], sA + row * 128 + cs * 16);
            }
            uint32_t bf[2][4];
#pragma unroll
            for (int nb = 0; nb < 2; nb++) {
                int krow = ks * 16 + (lane & 7) + ((lane >> 3) & 1) * 8;
                int nch = warp_ni * 4 + nb * 2 + (lane >> 4);
                int cs = (nch & 8) | ((nch & 7) ^ (krow & 7));
                ldm_x4_t(bf[nb], sB + krow * 256 + cs * 16);
            }
#pragma unroll
            for (int mi = 0; mi < 4; mi++)
#pragma unroll
                for (int ni = 0; ni < 4; ni++)
                    mma_h(acc[mi][ni], a[mi], &bf[ni >> 1][(ni & 1) * 2]);
        }
        if (kt + 1 < KT) stsA((kt + 1) & 1);
    }

    // epilogue: + bias, scale q by log2e, transposed f16 store
    int g = lane >> 2, tq = lane & 3;
    uint16_t* Y = (warp_mi == 0 ? g_qbT : g_kbT) + (size_t)b * NPOS * CQ;
    float scale = (warp_mi == 0) ? LOG2E : 1.0f;
#pragma unroll
    for (int mi = 0; mi < 4; mi++) {
        int o0 = mi * 16 + g;
        int o1 = o0 + 8;
        float bv0 = (warp_mi == 0) ? bq[o0] : bk[o0];
        float bv1 = (warp_mi == 0) ? bq[o1] : bk[o1];
#pragma unroll
        for (int ni = 0; ni < 4; ni++) {
            int ncol = n0 + warp_ni * 32 + ni * 8 + 2 * tq;
            Y[(size_t)ncol * CQ + o0]       = h16of((acc[mi][ni][0] + bv0) * scale);
            Y[(size_t)(ncol + 1) * CQ + o0] = h16of((acc[mi][ni][1] + bv0) * scale);
            Y[(size_t)ncol * CQ + o1]       = h16of((acc[mi][ni][2] + bv1) * scale);
            Y[(size_t)(ncol + 1) * CQ + o1] = h16of((acc[mi][ni][3] + bv1) * scale);
        }
    }
}

// ---------------------------------------------------------------------------
// proj_v (f16 mma): V[c][n] = sum_k Wv[c][k] * xb[k][n] + bv[c], store f16.
// ---------------------------------------------------------------------------
__global__ __launch_bounds__(256) void proj_v_kernel(
    const float* __restrict__ W, const float* __restrict__ bias)
{
    uint32_t sbase = smem_u32(smem);

    int tid = threadIdx.x, lane = tid & 31, wid = tid >> 5;
    int warp_mi = wid >> 2;
    int warp_ni = wid & 3;
    int b = blockIdx.z;
    int n0 = blockIdx.x * 128, c0 = blockIdx.y * 128;

    const uint16_t* X = g_xb + (size_t)b * C * NPOS;
    const int KT = C / 64;

    float aw[4][8];
    auto ldgA = [&](int kt) {
#pragma unroll
        for (int i = 0; i < 4; i++) {
            int idx = tid + i * 256;
            int r = idx >> 3, c = idx & 7;
            const float* src = W + (size_t)(c0 + r) * C + kt * 64 + c * 8;
            float4 v0 = *(const float4*)src;
            float4 v1 = *(const float4*)(src + 4);
            aw[i][0] = v0.x; aw[i][1] = v0.y; aw[i][2] = v0.z; aw[i][3] = v0.w;
            aw[i][4] = v1.x; aw[i][5] = v1.y; aw[i][6] = v1.z; aw[i][7] = v1.w;
        }
    };
    auto stsA = [&](int s) {
#pragma unroll
        for (int i = 0; i < 4; i++) {
            int idx = tid + i * 256;
            int r = idx >> 3, c = idx & 7;
            int cs = c ^ (r & 7);
            uint4 o;
            o.x = hpack(aw[i][0], aw[i][1]);
            o.y = hpack(aw[i][2], aw[i][3]);
            o.z = hpack(aw[i][4], aw[i][5]);
            o.w = hpack(aw[i][6], aw[i][7]);
            *(uint4*)(smem + s * 32768 + r * 128 + cs * 16) = o;
        }
    };
    auto cpaB = [&](int kt, int s) {
#pragma unroll
        for (int i = 0; i < 4; i++) {
            int idx = tid + i * 256;
            int r = idx >> 4, c = idx & 15;
            int cs = (c & 8) | ((c & 7) ^ (r & 7));
            cpa16(sbase + s * 32768 + 16384 + r * 256 + cs * 16,
                  X + (size_t)(kt * 64 + r) * NPOS + n0 + c * 8);
        }
        cpcommit();
    };

    float acc[4][4][4];
#pragma unroll
    for (int i = 0; i < 4; i++)
#pragma unroll
        for (int j = 0; j < 4; j++)
#pragma unroll
            for (int k = 0; k < 4; k++) acc[i][j][k] = 0.f;

    ldgA(0);
    cpaB(0, 0);
    stsA(0);

    for (int kt = 0; kt < KT; kt++) {
        cpwait<0>();
        __syncthreads();
        if (kt + 1 < KT) {
            cpaB(kt + 1, (kt + 1) & 1);
            ldgA(kt + 1);
        }
        uint32_t sA = sbase + (kt & 1) * 32768;
        uint32_t sB = sA + 16384;
#pragma unroll
        for (int ks = 0; ks < 4; ks++) {
            uint32_t a[4][4];
#pragma unroll
            for (int mi = 0; mi < 4; mi++) {
                int row = warp_mi * 64 + mi * 16 + (lane & 15);
                int ch = ks * 2 + (lane >> 4);
                int cs = ch ^ (row & 7);
                ldm_x4(a[mi], sA + row * 128 + cs * 16);
            }
            uint32_t bf[2][4];
#pragma unroll
            for (int nb = 0; nb < 2; nb++) {
                int krow = ks * 16 + (lane & 7) + ((lane >> 3) & 1) * 8;
                int nch = warp_ni * 4 + nb * 2 + (lane >> 4);
                int cs = (nch & 8) | ((nch & 7) ^ (krow & 7));
                ldm_x4_t(bf[nb], sB + krow * 256 + cs * 16);
            }
#pragma unroll
            for (int mi = 0; mi < 4; mi++)
#pragma unroll
                for (int ni = 0; ni < 4; ni++)
                    mma_h(acc[mi][ni], a[mi], &bf[ni >> 1][(ni & 1) * 2]);
        }
        if (kt + 1 < KT) stsA((kt + 1) & 1);
    }

    int g = lane >> 2, tq = lane & 3;
    uint16_t* Vout = g_v + (size_t)b * C * NPOS;
#pragma unroll
    for (int mi = 0; mi < 4; mi++) {
        int c_r0 = c0 + warp_mi * 64 + mi * 16 + g;
        int c_r1 = c_r0 + 8;
        float bv0 = bias[c_r0], bv1 = bias[c_r1];
#pragma unroll
        for (int ni = 0; ni < 4; ni++) {
            int ncol = n0 + warp_ni * 32 + ni * 8 + 2 * tq;
            *(uint32_t*)&Vout[(size_t)c_r0 * NPOS + ncol] =
                hpack(acc[mi][ni][0] + bv0, acc[mi][ni][1] + bv0);
            *(uint32_t*)&Vout[(size_t)c_r1 * NPOS + ncol] =
                hpack(acc[mi][ni][2] + bv1, acc[mi][ni][3] + bv1);
        }
    }
}

// ---------------------------------------------------------------------------
// Energy (f16 mma): acc[n][m] = E*log2e (q pre-scaled). Epilogue:
// P = 2^(acc - 4) via ex2.approx.f16x2; row sums via mma-with-ones on the
// freshly packed P fragments (accumulator->A-operand identity); atomicAdd.
// ---------------------------------------------------------------------------
__global__ __launch_bounds__(256) void energy_kernel()
{
    uint32_t sA = smem_u32(smem);
    uint32_t sB = sA + 16384;

    int tid = threadIdx.x, lane = tid & 31, wid = tid >> 5;
    int warp_mi = wid >> 2;        // n-dim (2 x 64)
    int warp_ni = wid & 3;         // m-dim (4 x 32)
    int b = blockIdx.z;
    int m0 = blockIdx.x * 128, n0 = blockIdx.y * 128;

    const uint16_t* Aq = g_qbT + ((size_t)b * NPOS + n0) * CQ;
    const uint16_t* Bk = g_kbT + ((size_t)b * NPOS + m0) * CQ;

#pragma unroll
    for (int i = 0; i < 4; i++) {
        int idx = i * 256 + tid;
        int r = idx >> 3, c = idx & 7;
        int cs = c ^ (r & 7);
        cpa16(sA + r * 128 + cs * 16, Aq + (size_t)r * CQ + c * 8);
        cpa16(sB + r * 128 + cs * 16, Bk + (size_t)r * CQ + c * 8);
    }
    cpcommit();
    cpwait<0>();
    __syncthreads();

    float acc[4][4][4];
#pragma unroll
    for (int i = 0; i < 4; i++)
#pragma unroll
        for (int j = 0; j < 4; j++)
#pragma unroll
            for (int k = 0; k < 4; k++) acc[i][j][k] = 0.f;

    int a_row_b = warp_mi * 64 + (lane & 15);
    int a_cadd = lane >> 4;
    int b_row_b = warp_ni * 32 + (lane & 7) + ((lane >> 4) << 3);
    int b_cadd = (lane >> 3) & 1;

#pragma unroll
    for (int ks = 0; ks < 4; ks++) {
        int kc = ks * 2;
        uint32_t a[4][4];
#pragma unroll
        for (int mi = 0; mi < 4; mi++) {
            int row = a_row_b + mi * 16;
            int cs = (kc + a_cadd) ^ (row & 7);
            ldm_x4(a[mi], sA + row * 128 + cs * 16);
        }
        uint32_t bf[2][4];
#pragma unroll
        for (int j2 = 0; j2 < 2; j2++) {
            int row = b_row_b + j2 * 16;
            int cs = (kc + b_cadd) ^ (row & 7);
            ldm_x4(bf[j2], sB + row * 128 + cs * 16);
        }
#pragma unroll
        for (int mi = 0; mi < 4; mi++)
#pragma unroll
            for (int ni = 0; ni < 4; ni++)
                mma_h(acc[mi][ni], a[mi], &bf[ni >> 1][(ni & 1) * 2]);
    }

    int g = lane >> 2, tq = lane & 3;
    uint16_t* Pout = g_P + (size_t)b * NPOS * NPOS;
    float* SUM = g_sum + b * NPOS;
    uint32_t onesb[2] = {0x3C003C00u, 0x3C003C00u};

#pragma unroll
    for (int mi = 0; mi < 4; mi++) {
        int r0 = n0 + warp_mi * 64 + mi * 16 + g;
        int r1 = r0 + 8;
        uint32_t e01[4], e23[4];
#pragma unroll
        for (int ni = 0; ni < 4; ni++) {
            e01[ni] = ex2h2(hpack(acc[mi][ni][0] - PSHIFT, acc[mi][ni][1] - PSHIFT));
            e23[ni] = ex2h2(hpack(acc[mi][ni][2] - PSHIFT, acc[mi][ni][3] - PSHIFT));
            int col = m0 + warp_ni * 32 + ni * 8 + 2 * tq;
            *(uint32_t*)&Pout[(size_t)r0 * NPOS + col] = e01[ni];
            *(uint32_t*)&Pout[(size_t)r1 * NPOS + col] = e23[ni];
        }
        float ss[4] = {0.f, 0.f, 0.f, 0.f};
        uint32_t A0[4] = {e01[0], e23[0], e01[1], e23[1]};
        uint32_t A1[4] = {e01[2], e23[2], e01[3], e23[3]};
        mma_h(ss, A0, onesb);
        mma_h(ss, A1, onesb);
        if (tq == 0) {
            atomicAdd(&SUM[r0], ss[0]);
            atomicAdd(&SUM[r1], ss[2]);
        }
    }
}

// ---------------------------------------------------------------------------
// Out (f16 mma, 256x128 tile, 3-stage): D[c][n] = sum_m V[c][m]*P[n][m]
// Epilogue: out = gamma*inv[n]*D + x.
// ---------------------------------------------------------------------------
__global__ __launch_bounds__(256) void out_kernel(
    const float* __restrict__ x, const float* __restrict__ gamma,
    float* __restrict__ out)
{
    uint32_t sbase = smem_u32(smem);

    int tid = threadIdx.x, lane = tid & 31, wid = tid >> 5;
    int warp_mi = wid >> 1;        // c-dim (4 x 64)
    int warp_ni = wid & 1;         // n-dim (2 x 64)
    int b = blockIdx.z;
    int n0 = blockIdx.x * 128, c0 = blockIdx.y * 256;

    const uint16_t* V = g_v + ((size_t)b * C + c0) * NPOS;
    const uint16_t* P = g_P + ((size_t)b * NPOS + n0) * NPOS;

    const int KT = NPOS / 64;
    const int STG = 49152;

    auto load_stage = [&](int s, int kt) {
        int mb = kt * 64;
        uint32_t st = sbase + s * STG;
#pragma unroll
        for (int i = 0; i < 8; i++) {
            int idx = i * 256 + tid;
            int r = idx >> 3, c = idx & 7;
            int cs = c ^ (r & 7);
            cpa16(st + r * 128 + cs * 16, V + (size_t)r * NPOS + mb + c * 8);
        }
#pragma unroll
        for (int i = 0; i < 4; i++) {
            int idx = i * 256 + tid;
            int r = idx >> 3, c = idx & 7;
            int cs = c ^ (r & 7);
            cpa16(st + 32768 + r * 128 + cs * 16, P + (size_t)r * NPOS + mb + c * 8);
        }
        cpcommit();
    };

    load_stage(0, 0);
    load_stage(1, 1);

    float acc[4][8][4];
#pragma unroll
    for (int i = 0; i < 4; i++)
#pragma unroll
        for (int j = 0; j < 8; j++)
#pragma unroll
            for (int k = 0; k < 4; k++) acc[i][j][k] = 0.f;

    int a_row_b = warp_mi * 64 + (lane & 15);
    int a_cadd = lane >> 4;
    int b_row_b = warp_ni * 64 + (lane & 7) + ((lane >> 4) << 3);
    int b_cadd = (lane >> 3) & 1;

    for (int kt = 0; kt < KT; kt++) {
        if (kt >= KT - 1) cpwait<0>(); else cpwait<1>();
        __syncthreads();
        if (kt + 2 < KT) load_stage((kt + 2) % 3, kt + 2);

        uint32_t sA = sbase + (kt % 3) * STG;
        uint32_t sB = sA + 32768;
#pragma unroll
        for (int ks = 0; ks < 4; ks++) {
            int kc = ks * 2;
            uint32_t a[4][4];
#pragma unroll
            for (int mi = 0; mi < 4; mi++) {
                int row = a_row_b + mi * 16;
                int cs = (kc + a_cadd) ^ (row & 7);
                ldm_x4(a[mi], sA + row * 128 + cs * 16);
            }
            uint32_t bf[4][4];
#pragma unroll
            for (int j2 = 0; j2 < 4; j2++) {
                int row = b_row_b + j2 * 16;
                int cs = (kc + b_cadd) ^ (row & 7);
                ldm_x4(bf[j2], sB + row * 128 + cs * 16);
            }
#pragma unroll
            for (int mi = 0; mi < 4; mi++)
#pragma unroll
                for (int ni = 0; ni < 8; ni++)
                    mma_h(acc[mi][ni], a[mi], &bf[ni >> 1][(ni & 1) * 2]);
        }
    }

    int g = lane >> 2, tq = lane & 3;
    float gm = gamma[0];
    float2 iv[8];
#pragma unroll
    for (int ni = 0; ni < 8; ni++) {
        int ncol = n0 + warp_ni * 64 + ni * 8 + 2 * tq;
        iv[ni] = *(const float2*)&g_inv[b * NPOS + ncol];
    }

#pragma unroll
    for (int mi = 0; mi < 4; mi++) {
        int c_r0 = c0 + warp_mi * 64 + mi * 16 + g;
        int c_r1 = c_r0 + 8;
#pragma unroll
        for (int ni = 0; ni < 8; ni++) {
            int ncol = n0 + warp_ni * 64 + ni * 8 + 2 * tq;
            size_t off0 = ((size_t)b * C + c_r0) * NPOS + ncol;
            size_t off1 = ((size_t)b * C + c_r1) * NPOS + ncol;
            float2 xv0 = *(const float2*)&x[off0];
            float2 xv1 = *(const float2*)&x[off1];
            float2 o0, o1;
            o0.x = gm * iv[ni].x * acc[mi][ni][0] + xv0.x;
            o0.y = gm * iv[ni].y * acc[mi][ni][1] + xv0.y;
            o1.x = gm * iv[ni].x * acc[mi][ni][2] + xv1.x;
            o1.y = gm * iv[ni].y * acc[mi][ni][3] + xv1.y;
            *(float2*)&out[off0] = o0;
            *(float2*)&out[off1] = o1;
        }
    }
}

// ---------------------------------------------------------------------------
extern "C" void kernel_launch(void* const* d_in, const int* in_sizes, int n_in,
                              void* d_out, int out_size)
{
    const float* x     = (const float*)d_in[0];
    const float* Wq    = (const float*)d_in[1];
    const float* bq    = (const float*)d_in[2];
    const float* Wk    = (const float*)d_in[3];
    const float* bk    = (const float*)d_in[4];
    const float* Wv    = (const float*)d_in[5];
    const float* bv    = (const float*)d_in[6];
    const float* gamma = (const float*)d_in[7];
    float* out = (float*)d_out;

    cudaFuncSetAttribute(proj_qk_kernel,
                         cudaFuncAttributeMaxDynamicSharedMemorySize, 65536);
    cudaFuncSetAttribute(proj_v_kernel,
                         cudaFuncAttributeMaxDynamicSharedMemorySize, 65536);
    cudaFuncSetAttribute(energy_kernel,
                         cudaFuncAttributeMaxDynamicSharedMemorySize, 32768);
    cudaFuncSetAttribute(out_kernel,
                         cudaFuncAttributeMaxDynamicSharedMemorySize, 147456);

    zero_kernel<<<(BATCH * NPOS) / 256, 256>>>();
    cvt_x_kernel<<<(int)((size_t)BATCH * C * NPOS / 4 / 256), 256>>>(x);

    proj_qk_kernel<<<dim3(NPOS / 128, 1, BATCH), 256, 65536>>>(Wq, bq, Wk, bk);
    proj_v_kernel<<<dim3(NPOS / 128, C / 128, BATCH), 256, 65536>>>(Wv, bv);

    energy_kernel<<<dim3(NPOS / 128, NPOS / 128, BATCH), 256, 32768>>>();
    inv_kernel<<<(BATCH * NPOS) / 256, 256>>>();

    out_kernel<<<dim3(NPOS / 128, C / 256, BATCH), 256, 147456>>>(x, gamma, out);
}